// round 10
// baseline (speedup 1.0000x reference)
#include <cuda_runtime.h>
#include <cuda_bf16.h>
#include <cstdint>
#include <math.h>

// Problem constants (B=1, S=2048, E=2048, D=64, H=32, KVH=8, group=4)
#define S_LEN 2048
#define E_DIM 2048
#define HEADS 32
#define KVH 8
#define HDIM 64
#define KV_DIM (KVH * HDIM)   // 512
#define KEXP (3 * E_DIM)      // 6144 : split-bf16 expanded K
#define DEXP (3 * HDIM)       // 192  : split-bf16 expanded head dim

// ---------------------------------------------------------------------------
// Scratch (device globals: runtime allocation is forbidden)
// ---------------------------------------------------------------------------
__device__ float g_q[S_LEN * E_DIM];      // [S, H, D] fp32 (pre-rope)
__device__ float g_k[S_LEN * KV_DIM];     // [S, KVH, D]
__device__ float g_v[S_LEN * KV_DIM];     // [S, KVH, D] fp32

__device__ __nv_bfloat16 g_xexp[S_LEN * KEXP];
__device__ __nv_bfloat16 g_wqexp[E_DIM * KEXP];
__device__ __nv_bfloat16 g_wkexp[KV_DIM * KEXP];
__device__ __nv_bfloat16 g_wvexp[KV_DIM * KEXP];
__device__ __nv_bfloat16 g_woexp[E_DIM * KEXP];
__device__ __nv_bfloat16 g_attexp[S_LEN * KEXP];   // attention out, expanded

__device__ __nv_bfloat16 g_qe[S_LEN * HEADS * DEXP];  // rope'd Q, expanded
__device__ __nv_bfloat16 g_ke[S_LEN * KVH * DEXP];    // rope'd K, expanded

__device__ __forceinline__ uint32_t smem_u32(const void* p) {
    uint32_t a;
    asm("{ .reg .u64 t; cvta.to.shared.u64 t, %1; cvt.u32.u64 %0, t; }"
        : "=r"(a) : "l"(p));
    return a;
}

__device__ __forceinline__ uint32_t pack_bf16x2(float lo, float hi) {
    __nv_bfloat162 t = __floats2bfloat162_rn(lo, hi);  // .x = lo half
    return *reinterpret_cast<uint32_t*>(&t);
}

// ---------------------------------------------------------------------------
// split-bf16 expansion: fp32 [rows,K] -> bf16 [rows,3K]
// modeB=0 (A side): [hi | hi | lo];  modeB=1 (B side): [hi | lo | hi]
// ---------------------------------------------------------------------------
__global__ void split_bf16(const float* __restrict__ in, __nv_bfloat16* __restrict__ out,
                           int rows, int K, int modeB)
{
    int n = rows * K;
    for (int idx = blockIdx.x * blockDim.x + threadIdx.x; idx < n;
         idx += gridDim.x * blockDim.x) {
        int r = idx / K, k = idx - r * K;
        float v = in[idx];
        __nv_bfloat16 h = __float2bfloat16(v);
        __nv_bfloat16 l = __float2bfloat16(v - __bfloat162float(h));
        __nv_bfloat16* o = out + (size_t)r * (3 * K);
        if (modeB) { o[k] = h; o[K + k] = l; o[2 * K + k] = h; }
        else       { o[k] = h; o[K + k] = h; o[2 * K + k] = l; }
    }
}

// ---------------------------------------------------------------------------
// bf16 GEMM via mma.sync (HMMA): C[M,N] fp32 = A[M,K'] @ B[N,K']^T
// ---------------------------------------------------------------------------
#define GBK 32
#define ROWB 80
#define TILEB (128 * ROWB)

__global__ __launch_bounds__(256) void mma_gemm(
    const __nv_bfloat16* __restrict__ A, const __nv_bfloat16* __restrict__ B,
    float* __restrict__ C, int M, int N, int K)
{
    __shared__ __align__(16) uint8_t sm[4 * TILEB];
    const uint32_t sb = smem_u32(sm);

    const int tid  = threadIdx.x;
    const int lane = tid & 31;
    const int wid  = tid >> 5;
    const int wm   = wid & 1;
    const int wn   = wid >> 1;
    const int bm   = blockIdx.y * 128;
    const int bn   = blockIdx.x * 128;

    float acc[4][4][4];
    #pragma unroll
    for (int i = 0; i < 4; i++)
        #pragma unroll
        for (int j = 0; j < 4; j++)
            #pragma unroll
            for (int c = 0; c < 4; c++) acc[i][j][c] = 0.f;

    uint32_t aoff[4], boff[2];
    {
        const int l7 = lane & 7;
        const int rA = ((lane >> 3) & 1) * 8;
        const int kA = ((lane >> 4) & 1) * 16;
        #pragma unroll
        for (int mb = 0; mb < 4; mb++)
            aoff[mb] = (uint32_t)((wm * 64 + mb * 16 + l7 + rA) * ROWB + kA);
        const int rB = ((lane >> 4) & 1) * 8;
        const int kB = ((lane >> 3) & 1) * 16;
        #pragma unroll
        for (int p = 0; p < 2; p++)
            boff[p] = (uint32_t)((wn * 32 + p * 16 + l7 + rB) * ROWB + kB);
    }

    const int NKC = K / GBK;

    auto load_tiles = [&](int k0, int which) {
        uint32_t da = sb + which * TILEB;
        uint32_t db = sb + (2 + which) * TILEB;
        #pragma unroll
        for (int i = 0; i < 2; i++) {
            int c  = tid + 256 * i;
            int r  = c >> 2;
            int cc = c & 3;
            uint32_t dsta = da + r * ROWB + cc * 16;
            uint32_t dstb = db + r * ROWB + cc * 16;
            const __nv_bfloat16* sa  = A + (size_t)(bm + r) * K + k0 + cc * 8;
            const __nv_bfloat16* sbp = B + (size_t)(bn + r) * K + k0 + cc * 8;
            asm volatile("cp.async.cg.shared.global [%0], [%1], 16;" :: "r"(dsta), "l"(sa) : "memory");
            asm volatile("cp.async.cg.shared.global [%0], [%1], 16;" :: "r"(dstb), "l"(sbp) : "memory");
        }
    };

    load_tiles(0, 0);
    asm volatile("cp.async.commit_group;" ::: "memory");
    load_tiles(GBK, 1);
    asm volatile("cp.async.commit_group;" ::: "memory");

    for (int kc = 0; kc < NKC; kc++) {
        asm volatile("cp.async.wait_group 1;" ::: "memory");
        __syncthreads();

        const int which = kc & 1;
        const uint32_t abuf = sb + which * TILEB;
        const uint32_t bbuf = sb + (2 + which) * TILEB;

        #pragma unroll
        for (int ks = 0; ks < 2; ks++) {
            uint32_t af[4][4], bfr[4][2];
            #pragma unroll
            for (int mb = 0; mb < 4; mb++) {
                uint32_t addr = abuf + aoff[mb] + ks * 32;
                asm volatile("ldmatrix.sync.aligned.m8n8.x4.shared.b16 {%0,%1,%2,%3}, [%4];"
                             : "=r"(af[mb][0]), "=r"(af[mb][1]), "=r"(af[mb][2]), "=r"(af[mb][3])
                             : "r"(addr));
            }
            #pragma unroll
            for (int p = 0; p < 2; p++) {
                uint32_t addr = bbuf + boff[p] + ks * 32;
                asm volatile("ldmatrix.sync.aligned.m8n8.x4.shared.b16 {%0,%1,%2,%3}, [%4];"
                             : "=r"(bfr[2 * p][0]), "=r"(bfr[2 * p][1]),
                               "=r"(bfr[2 * p + 1][0]), "=r"(bfr[2 * p + 1][1])
                             : "r"(addr));
            }
            #pragma unroll
            for (int mb = 0; mb < 4; mb++)
                #pragma unroll
                for (int nb = 0; nb < 4; nb++) {
                    asm volatile(
                        "mma.sync.aligned.m16n8k16.row.col.f32.bf16.bf16.f32 "
                        "{%0,%1,%2,%3}, {%4,%5,%6,%7}, {%8,%9}, {%0,%1,%2,%3};"
                        : "+f"(acc[mb][nb][0]), "+f"(acc[mb][nb][1]),
                          "+f"(acc[mb][nb][2]), "+f"(acc[mb][nb][3])
                        : "r"(af[mb][0]), "r"(af[mb][1]), "r"(af[mb][2]), "r"(af[mb][3]),
                          "r"(bfr[nb][0]), "r"(bfr[nb][1]));
                }
        }

        __syncthreads();
        if (kc + 2 < NKC) load_tiles((kc + 2) * GBK, which);
        asm volatile("cp.async.commit_group;" ::: "memory");
    }

    const int g  = lane >> 2;
    const int tc = (lane & 3) * 2;
    #pragma unroll
    for (int mb = 0; mb < 4; mb++) {
        const int row0 = bm + wm * 64 + mb * 16 + g;
        #pragma unroll
        for (int nb = 0; nb < 4; nb++) {
            const int col = bn + wn * 32 + nb * 8 + tc;
            *(float2*)&C[(size_t)row0 * N + col]       = make_float2(acc[mb][nb][0], acc[mb][nb][1]);
            *(float2*)&C[(size_t)(row0 + 8) * N + col] = make_float2(acc[mb][nb][2], acc[mb][nb][3]);
        }
    }
}

// ---------------------------------------------------------------------------
// RoPE + split-bf16 expansion: fp32 [S,NH,64] -> bf16 [S,NH,192]
// modeB=0 (Q, A side [h|h|l]); modeB=1 (K, B side [h|l|h])
// ---------------------------------------------------------------------------
__global__ void rope_expand(const float* __restrict__ src, __nv_bfloat16* __restrict__ dst,
                            const float* __restrict__ cosb, const float* __restrict__ sinb,
                            int NH, int modeB)
{
    const int s = blockIdx.x;
    const int h = threadIdx.x >> 5;
    const int d = threadIdx.x & 31;
    const float* p = src + ((size_t)s * NH + h) * HDIM;
    const float c  = cosb[s * HDIM + d];
    const float sn = sinb[s * HDIM + d];
    const float a = p[d], b = p[d + 32];
    const float v0 = a * c - b * sn;   // position d
    const float v1 = b * c + a * sn;   // position d+32

    __nv_bfloat16 h0 = __float2bfloat16(v0);
    __nv_bfloat16 l0 = __float2bfloat16(v0 - __bfloat162float(h0));
    __nv_bfloat16 h1 = __float2bfloat16(v1);
    __nv_bfloat16 l1 = __float2bfloat16(v1 - __bfloat162float(h1));

    __nv_bfloat16* o = dst + ((size_t)s * NH + h) * DEXP;
    if (modeB) {
        o[d] = h0; o[64 + d] = l0; o[128 + d] = h0;
        o[d + 32] = h1; o[96 + d] = l1; o[160 + d] = h1;
    } else {
        o[d] = h0; o[64 + d] = h0; o[128 + d] = l0;
        o[d + 32] = h1; o[96 + d] = h1; o[160 + d] = l1;
    }
}

// ---------------------------------------------------------------------------
// Flash attention on HMMA, full split-bf16 precision on QK AND PV.
// Qe [S,H,192], Ke [S,KVH,192] expanded; V [S,KVH,64] fp32 (split at load).
// Output: split-bf16 expanded rows directly into atte [S, 3*E].
// Block: 128 thr (4 warps x m16 rows). BQ=64, BKT=64.
// V smem: [d=64 rows][keys: vh(0..63) | vl(64..127)], row stride ROWV.
// PV: O = Ph*Vh + Ph*Vl + Pl*Vh  (3 passes of 4 k-steps)
// ---------------------------------------------------------------------------
#define ROWQ 400              // smem row stride for 192 bf16 (+pad)
#define ROWV 272              // smem row stride for 128 bf16 (vh|vl) + pad
#define SQ_OFF 0
#define SK_OFF (64 * ROWQ)                 // 25600
#define SV_OFF (2 * 64 * ROWQ)             // 51200
#define ATTN_SMEM (2 * 64 * ROWQ + 64 * ROWV)  // 68608

__global__ __launch_bounds__(128) void attn_mma(
    const __nv_bfloat16* __restrict__ Qe, const __nv_bfloat16* __restrict__ Ke,
    const float* __restrict__ V, __nv_bfloat16* __restrict__ atte)
{
    extern __shared__ __align__(16) uint8_t sm[];
    const uint32_t sb = smem_u32(sm);

    const int qb  = (int)gridDim.x - 1 - blockIdx.x;   // heavy blocks first
    const int h   = blockIdx.y;
    const int kvh = h >> 2;

    const int tid  = threadIdx.x;
    const int lane = tid & 31;
    const int w    = tid >> 5;

    const int l7  = lane & 7;
    const int l8  = (lane >> 3) & 1;
    const int l16 = (lane >> 4) & 1;
    const int g   = lane >> 2;
    const int t4  = lane & 3;

    // fragment base offsets
    const uint32_t qoff = sb + SQ_OFF + (uint32_t)(w * 16 + l7 + l8 * 8) * ROWQ + l16 * 16;
    const uint32_t koff = sb + SK_OFF + (uint32_t)(l7 + l16 * 8) * ROWQ + l8 * 16;
    const uint32_t voff = sb + SV_OFF + (uint32_t)(l7 + l16 * 8) * ROWV + l8 * 16;

    // Load Q tile: 64 rows x 192 bf16 = 1536 16B chunks, 12 per thread
    #pragma unroll
    for (int i = 0; i < 12; i++) {
        int idx = tid + 128 * i;
        int r = idx / 24, c = idx % 24;
        uint32_t dst = sb + SQ_OFF + r * ROWQ + c * 16;
        const __nv_bfloat16* src = Qe + ((size_t)(qb * 64 + r) * HEADS + h) * DEXP + c * 8;
        asm volatile("cp.async.cg.shared.global [%0], [%1], 16;" :: "r"(dst), "l"(src) : "memory");
    }
    asm volatile("cp.async.commit_group;" ::: "memory");

    float m0 = -1e30f, m1 = -1e30f, l0 = 0.f, l1 = 0.f;
    float oacc[8][4];
    #pragma unroll
    for (int t = 0; t < 8; t++)
        #pragma unroll
        for (int j = 0; j < 4; j++) oacc[t][j] = 0.f;

    const float scale = 0.125f;
    const int row_g0 = qb * 64 + w * 16 + g;      // global q row for c0,c1
    const int row_g1 = row_g0 + 8;                // for c2,c3
    const int nkb = qb + 1;

    for (int kb = 0; kb < nkb; kb++) {
        // K tile (cp.async)
        #pragma unroll
        for (int i = 0; i < 12; i++) {
            int idx = tid + 128 * i;
            int r = idx / 24, c = idx % 24;
            uint32_t dst = sb + SK_OFF + r * ROWQ + c * 16;
            const __nv_bfloat16* src = Ke + ((size_t)(kb * 64 + r) * KVH + kvh) * DEXP + c * 8;
            asm volatile("cp.async.cg.shared.global [%0], [%1], 16;" :: "r"(dst), "l"(src) : "memory");
        }
        // V tile: fp32 load, split into (vh, vl), transposed store: smem [d][key]
        #pragma unroll
        for (int i = 0; i < 8; i++) {
            int idx = tid + 128 * i;       // 0..1023
            int r = idx >> 4;              // key row 0..63
            int c = idx & 15;              // d chunk of 4 floats
            float4 vv = *(const float4*)(V + ((size_t)(kb * 64 + r) * KVH + kvh) * HDIM + c * 4);
            const float* pv = (const float*)&vv;
            #pragma unroll
            for (int j = 0; j < 4; j++) {
                float fv = pv[j];
                __nv_bfloat16 vh = __float2bfloat16(fv);
                __nv_bfloat16 vl = __float2bfloat16(fv - __bfloat162float(vh));
                uint8_t* rowp = sm + SV_OFF + (c * 4 + j) * ROWV;
                *(__nv_bfloat16*)(rowp + r * 2)       = vh;
                *(__nv_bfloat16*)(rowp + 128 + r * 2) = vl;
            }
        }
        asm volatile("cp.async.commit_group;" ::: "memory");
        asm volatile("cp.async.wait_group 0;" ::: "memory");
        __syncthreads();

        // ---- QK: S[16 x 64] over k=192 ----
        float sacc[8][4];
        #pragma unroll
        for (int t = 0; t < 8; t++)
            #pragma unroll
            for (int j = 0; j < 4; j++) sacc[t][j] = 0.f;

        #pragma unroll
        for (int ks = 0; ks < 12; ks++) {
            uint32_t a0, a1, a2, a3;
            asm volatile("ldmatrix.sync.aligned.m8n8.x4.shared.b16 {%0,%1,%2,%3}, [%4];"
                         : "=r"(a0), "=r"(a1), "=r"(a2), "=r"(a3)
                         : "r"(qoff + ks * 32));
            uint32_t bq[8][2];
            #pragma unroll
            for (int p = 0; p < 4; p++) {
                asm volatile("ldmatrix.sync.aligned.m8n8.x4.shared.b16 {%0,%1,%2,%3}, [%4];"
                             : "=r"(bq[2 * p][0]), "=r"(bq[2 * p][1]),
                               "=r"(bq[2 * p + 1][0]), "=r"(bq[2 * p + 1][1])
                             : "r"(koff + p * 16 * ROWQ + ks * 32));
            }
            #pragma unroll
            for (int t = 0; t < 8; t++) {
                asm volatile(
                    "mma.sync.aligned.m16n8k16.row.col.f32.bf16.bf16.f32 "
                    "{%0,%1,%2,%3}, {%4,%5,%6,%7}, {%8,%9}, {%0,%1,%2,%3};"
                    : "+f"(sacc[t][0]), "+f"(sacc[t][1]), "+f"(sacc[t][2]), "+f"(sacc[t][3])
                    : "r"(a0), "r"(a1), "r"(a2), "r"(a3), "r"(bq[t][0]), "r"(bq[t][1]));
            }
        }

        // ---- scale + causal mask ----
        #pragma unroll
        for (int t = 0; t < 8; t++) {
            const int c0 = kb * 64 + t * 8 + 2 * t4;
            sacc[t][0] = (c0     <= row_g0) ? sacc[t][0] * scale : -1e30f;
            sacc[t][1] = (c0 + 1 <= row_g0) ? sacc[t][1] * scale : -1e30f;
            sacc[t][2] = (c0     <= row_g1) ? sacc[t][2] * scale : -1e30f;
            sacc[t][3] = (c0 + 1 <= row_g1) ? sacc[t][3] * scale : -1e30f;
        }

        // ---- online softmax ----
        float rm0 = -1e30f, rm1 = -1e30f;
        #pragma unroll
        for (int t = 0; t < 8; t++) {
            rm0 = fmaxf(rm0, fmaxf(sacc[t][0], sacc[t][1]));
            rm1 = fmaxf(rm1, fmaxf(sacc[t][2], sacc[t][3]));
        }
        #pragma unroll
        for (int off = 1; off <= 2; off <<= 1) {
            rm0 = fmaxf(rm0, __shfl_xor_sync(0xffffffffu, rm0, off));
            rm1 = fmaxf(rm1, __shfl_xor_sync(0xffffffffu, rm1, off));
        }
        const float mn0 = fmaxf(m0, rm0), mn1 = fmaxf(m1, rm1);
        const float al0 = __expf(m0 - mn0), al1 = __expf(m1 - mn1);
        m0 = mn0; m1 = mn1;

        float rs0 = 0.f, rs1 = 0.f;
        #pragma unroll
        for (int t = 0; t < 8; t++) {
            sacc[t][0] = __expf(sacc[t][0] - mn0);
            sacc[t][1] = __expf(sacc[t][1] - mn0);
            sacc[t][2] = __expf(sacc[t][2] - mn1);
            sacc[t][3] = __expf(sacc[t][3] - mn1);
            rs0 += sacc[t][0] + sacc[t][1];
            rs1 += sacc[t][2] + sacc[t][3];
        }
        #pragma unroll
        for (int off = 1; off <= 2; off <<= 1) {
            rs0 += __shfl_xor_sync(0xffffffffu, rs0, off);
            rs1 += __shfl_xor_sync(0xffffffffu, rs1, off);
        }
        l0 = l0 * al0 + rs0;
        l1 = l1 * al1 + rs1;

        #pragma unroll
        for (int t = 0; t < 8; t++) {
            oacc[t][0] *= al0; oacc[t][1] *= al0;
            oacc[t][2] *= al1; oacc[t][3] *= al1;
        }

        // ---- PV (split precision): O += Ph*Vh + Ph*Vl + Pl*Vh ----
        #pragma unroll
        for (int kk = 0; kk < 4; kk++) {
            // P hi fragments + lo residual fragments for this 16-key chunk
            const float s00 = sacc[2 * kk][0],     s01 = sacc[2 * kk][1];
            const float s02 = sacc[2 * kk][2],     s03 = sacc[2 * kk][3];
            const float s10 = sacc[2 * kk + 1][0], s11 = sacc[2 * kk + 1][1];
            const float s12 = sacc[2 * kk + 1][2], s13 = sacc[2 * kk + 1][3];
            __nv_bfloat16 h00 = __float2bfloat16(s00), h01 = __float2bfloat16(s01);
            __nv_bfloat16 h02 = __float2bfloat16(s02), h03 = __float2bfloat16(s03);
            __nv_bfloat16 h10 = __float2bfloat16(s10), h11 = __float2bfloat16(s11);
            __nv_bfloat16 h12 = __float2bfloat16(s12), h13 = __float2bfloat16(s13);
            uint32_t pa0 = pack_bf16x2(__bfloat162float(h00), __bfloat162float(h01));
            uint32_t pa1 = pack_bf16x2(__bfloat162float(h02), __bfloat162float(h03));
            uint32_t pa2 = pack_bf16x2(__bfloat162float(h10), __bfloat162float(h11));
            uint32_t pa3 = pack_bf16x2(__bfloat162float(h12), __bfloat162float(h13));
            uint32_t la0 = pack_bf16x2(s00 - __bfloat162float(h00), s01 - __bfloat162float(h01));
            uint32_t la1 = pack_bf16x2(s02 - __bfloat162float(h02), s03 - __bfloat162float(h03));
            uint32_t la2 = pack_bf16x2(s10 - __bfloat162float(h10), s11 - __bfloat162float(h11));
            uint32_t la3 = pack_bf16x2(s12 - __bfloat162float(h12), s13 - __bfloat162float(h13));

            uint32_t bv[8][2];
            // Vh fragments for this key chunk
            #pragma unroll
            for (int p = 0; p < 4; p++) {
                asm volatile("ldmatrix.sync.aligned.m8n8.x4.shared.b16 {%0,%1,%2,%3}, [%4];"
                             : "=r"(bv[2 * p][0]), "=r"(bv[2 * p][1]),
                               "=r"(bv[2 * p + 1][0]), "=r"(bv[2 * p + 1][1])
                             : "r"(voff + p * 16 * ROWV + kk * 32));
            }
            #pragma unroll
            for (int t = 0; t < 8; t++) {  // Ph * Vh
                asm volatile(
                    "mma.sync.aligned.m16n8k16.row.col.f32.bf16.bf16.f32 "
                    "{%0,%1,%2,%3}, {%4,%5,%6,%7}, {%8,%9}, {%0,%1,%2,%3};"
                    : "+f"(oacc[t][0]), "+f"(oacc[t][1]), "+f"(oacc[t][2]), "+f"(oacc[t][3])
                    : "r"(pa0), "r"(pa1), "r"(pa2), "r"(pa3), "r"(bv[t][0]), "r"(bv[t][1]));
            }
            #pragma unroll
            for (int t = 0; t < 8; t++) {  // Pl * Vh (reuse Vh fragments)
                asm volatile(
                    "mma.sync.aligned.m16n8k16.row.col.f32.bf16.bf16.f32 "
                    "{%0,%1,%2,%3}, {%4,%5,%6,%7}, {%8,%9}, {%0,%1,%2,%3};"
                    : "+f"(oacc[t][0]), "+f"(oacc[t][1]), "+f"(oacc[t][2]), "+f"(oacc[t][3])
                    : "r"(la0), "r"(la1), "r"(la2), "r"(la3), "r"(bv[t][0]), "r"(bv[t][1]));
            }
            // Vl fragments (key columns offset by 64 -> byte offset +128)
            #pragma unroll
            for (int p = 0; p < 4; p++) {
                asm volatile("ldmatrix.sync.aligned.m8n8.x4.shared.b16 {%0,%1,%2,%3}, [%4];"
                             : "=r"(bv[2 * p][0]), "=r"(bv[2 * p][1]),
                               "=r"(bv[2 * p + 1][0]), "=r"(bv[2 * p + 1][1])
                             : "r"(voff + p * 16 * ROWV + 128 + kk * 32));
            }
            #pragma unroll
            for (int t = 0; t < 8; t++) {  // Ph * Vl
                asm volatile(
                    "mma.sync.aligned.m16n8k16.row.col.f32.bf16.bf16.f32 "
                    "{%0,%1,%2,%3}, {%4,%5,%6,%7}, {%8,%9}, {%0,%1,%2,%3};"
                    : "+f"(oacc[t][0]), "+f"(oacc[t][1]), "+f"(oacc[t][2]), "+f"(oacc[t][3])
                    : "r"(pa0), "r"(pa1), "r"(pa2), "r"(pa3), "r"(bv[t][0]), "r"(bv[t][1]));
            }
        }
        __syncthreads();
    }

    // ---- epilogue: normalize + split-bf16 expand directly into atte ----
    const float inv0 = 1.0f / l0;
    const float inv1 = 1.0f / l1;
    #pragma unroll
    for (int t = 0; t < 8; t++) {
        const int col = h * HDIM + t * 8 + 2 * t4;   // 0..2047
        {
            float v0 = oacc[t][0] * inv0, v1 = oacc[t][1] * inv0;
            __nv_bfloat16 h0 = __float2bfloat16(v0), h1 = __float2bfloat16(v1);
            uint32_t hp = pack_bf16x2(__bfloat162float(h0), __bfloat162float(h1));
            uint32_t lp = pack_bf16x2(v0 - __bfloat162float(h0), v1 - __bfloat162float(h1));
            __nv_bfloat16* o = atte + (size_t)row_g0 * KEXP;
            *(uint32_t*)(o + col)              = hp;
            *(uint32_t*)(o + E_DIM + col)      = hp;
            *(uint32_t*)(o + 2 * E_DIM + col)  = lp;
        }
        {
            float v0 = oacc[t][2] * inv1, v1 = oacc[t][3] * inv1;
            __nv_bfloat16 h0 = __float2bfloat16(v0), h1 = __float2bfloat16(v1);
            uint32_t hp = pack_bf16x2(__bfloat162float(h0), __bfloat162float(h1));
            uint32_t lp = pack_bf16x2(v0 - __bfloat162float(h0), v1 - __bfloat162float(h1));
            __nv_bfloat16* o = atte + (size_t)row_g1 * KEXP;
            *(uint32_t*)(o + col)              = hp;
            *(uint32_t*)(o + E_DIM + col)      = hp;
            *(uint32_t*)(o + 2 * E_DIM + col)  = lp;
        }
    }
}

// ---------------------------------------------------------------------------
// Launch. Inputs: 0:x 1:Wq 2:Wk 3:Wv 4:Wo 5:cos 6:sin 7:attn_mask 8:last_pos
// ---------------------------------------------------------------------------
extern "C" void kernel_launch(void* const* d_in, const int* in_sizes, int n_in,
                              void* d_out, int out_size)
{
    const float* x    = (const float*)d_in[0];
    const float* Wq   = (const float*)d_in[1];
    const float* Wk   = (const float*)d_in[2];
    const float* Wv   = (const float*)d_in[3];
    const float* Wo   = (const float*)d_in[4];
    const float* cosb = (const float*)d_in[5];
    const float* sinb = (const float*)d_in[6];
    float* out = (float*)d_out;

    float *q, *k, *v;
    __nv_bfloat16 *xe, *wqe, *wke, *wve, *woe, *atte, *qe, *ke;
    cudaGetSymbolAddress((void**)&q,    g_q);
    cudaGetSymbolAddress((void**)&k,    g_k);
    cudaGetSymbolAddress((void**)&v,    g_v);
    cudaGetSymbolAddress((void**)&xe,   g_xexp);
    cudaGetSymbolAddress((void**)&wqe,  g_wqexp);
    cudaGetSymbolAddress((void**)&wke,  g_wkexp);
    cudaGetSymbolAddress((void**)&wve,  g_wvexp);
    cudaGetSymbolAddress((void**)&woe,  g_woexp);
    cudaGetSymbolAddress((void**)&atte, g_attexp);
    cudaGetSymbolAddress((void**)&qe,   g_qe);
    cudaGetSymbolAddress((void**)&ke,   g_ke);

    cudaFuncSetAttribute(attn_mma, cudaFuncAttributeMaxDynamicSharedMemorySize, ATTN_SMEM);

    // Split-bf16 expansion of GEMM operands
    split_bf16<<<4096, 256>>>(x,  xe,  S_LEN,  E_DIM, 0);
    split_bf16<<<4096, 256>>>(Wq, wqe, E_DIM,  E_DIM, 1);
    split_bf16<<<1024, 256>>>(Wk, wke, KV_DIM, E_DIM, 1);
    split_bf16<<<1024, 256>>>(Wv, wve, KV_DIM, E_DIM, 1);
    split_bf16<<<4096, 256>>>(Wo, woe, E_DIM,  E_DIM, 1);

    // QKV projections (HMMA)
    mma_gemm<<<dim3(E_DIM / 128,  S_LEN / 128), 256>>>(xe, wqe, q, S_LEN, E_DIM,  KEXP);
    mma_gemm<<<dim3(KV_DIM / 128, S_LEN / 128), 256>>>(xe, wke, k, S_LEN, KV_DIM, KEXP);
    mma_gemm<<<dim3(KV_DIM / 128, S_LEN / 128), 256>>>(xe, wve, v, S_LEN, KV_DIM, KEXP);

    // RoPE + expand Q/K
    rope_expand<<<S_LEN, HEADS * 32>>>(q, qe, cosb, sinb, HEADS, 0);
    rope_expand<<<S_LEN, KVH * 32>>>(k, ke, cosb, sinb, KVH, 1);

    // Flash attention (HMMA, split precision), writes expanded output directly
    attn_mma<<<dim3(S_LEN / 64, HEADS), 128, ATTN_SMEM>>>(qe, ke, v, atte);

    // Output projection (HMMA)
    mma_gemm<<<dim3(E_DIM / 128, S_LEN / 128), 256>>>(atte, woe, out, S_LEN, E_DIM, KEXP);
}

// round 11
// speedup vs baseline: 1.6522x; 1.6522x over previous
#include <cuda_runtime.h>
#include <cuda_bf16.h>
#include <cstdint>
#include <math.h>

// Problem constants (B=1, S=2048, E=2048, D=64, H=32, KVH=8, group=4)
#define S_LEN 2048
#define E_DIM 2048
#define HEADS 32
#define KVH 8
#define HDIM 64
#define KV_DIM (KVH * HDIM)   // 512
#define KEXP (3 * E_DIM)      // 6144 : split-bf16 expanded K
#define DEXP (3 * HDIM)       // 192  : split-bf16 expanded head dim
#define NKB_TOT (S_LEN / 64)  // 32 key blocks

// ---------------------------------------------------------------------------
// Scratch (device globals: runtime allocation is forbidden)
// ---------------------------------------------------------------------------
__device__ float g_q[S_LEN * E_DIM];
__device__ float g_k[S_LEN * KV_DIM];
__device__ float g_v[S_LEN * KV_DIM];

__device__ __nv_bfloat16 g_xexp[S_LEN * KEXP];
__device__ __nv_bfloat16 g_wqexp[E_DIM * KEXP];
__device__ __nv_bfloat16 g_wkexp[KV_DIM * KEXP];
__device__ __nv_bfloat16 g_wvexp[KV_DIM * KEXP];
__device__ __nv_bfloat16 g_woexp[E_DIM * KEXP];
__device__ __nv_bfloat16 g_attexp[S_LEN * KEXP];

__device__ __nv_bfloat16 g_qe[S_LEN * HEADS * DEXP];
__device__ __nv_bfloat16 g_ke[S_LEN * KVH * DEXP];
// V transposed + split: [kvh][kb][d=64][key: vh(0..63) | vl(64..127)]
__device__ __nv_bfloat16 g_vte[KVH * NKB_TOT * 64 * 128];

__device__ __forceinline__ uint32_t smem_u32(const void* p) {
    uint32_t a;
    asm("{ .reg .u64 t; cvta.to.shared.u64 t, %1; cvt.u32.u64 %0, t; }"
        : "=r"(a) : "l"(p));
    return a;
}

__device__ __forceinline__ uint32_t pack_bf16x2(float lo, float hi) {
    __nv_bfloat162 t = __floats2bfloat162_rn(lo, hi);
    return *reinterpret_cast<uint32_t*>(&t);
}

__device__ __forceinline__ float ex2f(float x) {
    float y;
    asm("ex2.approx.f32 %0, %1;" : "=f"(y) : "f"(x));
    return y;
}

// ---------------------------------------------------------------------------
// split-bf16 expansion: fp32 [rows,K] -> bf16 [rows,3K]
// ---------------------------------------------------------------------------
__global__ void split_bf16(const float* __restrict__ in, __nv_bfloat16* __restrict__ out,
                           int rows, int K, int modeB)
{
    int n = rows * K;
    for (int idx = blockIdx.x * blockDim.x + threadIdx.x; idx < n;
         idx += gridDim.x * blockDim.x) {
        int r = idx / K, k = idx - r * K;
        float v = in[idx];
        __nv_bfloat16 h = __float2bfloat16(v);
        __nv_bfloat16 l = __float2bfloat16(v - __bfloat162float(h));
        __nv_bfloat16* o = out + (size_t)r * (3 * K);
        if (modeB) { o[k] = h; o[K + k] = l; o[2 * K + k] = h; }
        else       { o[k] = h; o[K + k] = h; o[2 * K + k] = l; }
    }
}

// ---------------------------------------------------------------------------
// bf16 GEMM via mma.sync (unchanged, validated)
// ---------------------------------------------------------------------------
#define GBK 32
#define ROWB 80
#define TILEB (128 * ROWB)

__global__ __launch_bounds__(256) void mma_gemm(
    const __nv_bfloat16* __restrict__ A, const __nv_bfloat16* __restrict__ B,
    float* __restrict__ C, int M, int N, int K)
{
    __shared__ __align__(16) uint8_t sm[4 * TILEB];
    const uint32_t sb = smem_u32(sm);

    const int tid  = threadIdx.x;
    const int lane = tid & 31;
    const int wid  = tid >> 5;
    const int wm   = wid & 1;
    const int wn   = wid >> 1;
    const int bm   = blockIdx.y * 128;
    const int bn   = blockIdx.x * 128;

    float acc[4][4][4];
    #pragma unroll
    for (int i = 0; i < 4; i++)
        #pragma unroll
        for (int j = 0; j < 4; j++)
            #pragma unroll
            for (int c = 0; c < 4; c++) acc[i][j][c] = 0.f;

    uint32_t aoff[4], boff[2];
    {
        const int l7 = lane & 7;
        const int rA = ((lane >> 3) & 1) * 8;
        const int kA = ((lane >> 4) & 1) * 16;
        #pragma unroll
        for (int mb = 0; mb < 4; mb++)
            aoff[mb] = (uint32_t)((wm * 64 + mb * 16 + l7 + rA) * ROWB + kA);
        const int rB = ((lane >> 4) & 1) * 8;
        const int kB = ((lane >> 3) & 1) * 16;
        #pragma unroll
        for (int p = 0; p < 2; p++)
            boff[p] = (uint32_t)((wn * 32 + p * 16 + l7 + rB) * ROWB + kB);
    }

    const int NKC = K / GBK;

    auto load_tiles = [&](int k0, int which) {
        uint32_t da = sb + which * TILEB;
        uint32_t db = sb + (2 + which) * TILEB;
        #pragma unroll
        for (int i = 0; i < 2; i++) {
            int c  = tid + 256 * i;
            int r  = c >> 2;
            int cc = c & 3;
            uint32_t dsta = da + r * ROWB + cc * 16;
            uint32_t dstb = db + r * ROWB + cc * 16;
            const __nv_bfloat16* sa  = A + (size_t)(bm + r) * K + k0 + cc * 8;
            const __nv_bfloat16* sbp = B + (size_t)(bn + r) * K + k0 + cc * 8;
            asm volatile("cp.async.cg.shared.global [%0], [%1], 16;" :: "r"(dsta), "l"(sa) : "memory");
            asm volatile("cp.async.cg.shared.global [%0], [%1], 16;" :: "r"(dstb), "l"(sbp) : "memory");
        }
    };

    load_tiles(0, 0);
    asm volatile("cp.async.commit_group;" ::: "memory");
    load_tiles(GBK, 1);
    asm volatile("cp.async.commit_group;" ::: "memory");

    for (int kc = 0; kc < NKC; kc++) {
        asm volatile("cp.async.wait_group 1;" ::: "memory");
        __syncthreads();

        const int which = kc & 1;
        const uint32_t abuf = sb + which * TILEB;
        const uint32_t bbuf = sb + (2 + which) * TILEB;

        #pragma unroll
        for (int ks = 0; ks < 2; ks++) {
            uint32_t af[4][4], bfr[4][2];
            #pragma unroll
            for (int mb = 0; mb < 4; mb++) {
                uint32_t addr = abuf + aoff[mb] + ks * 32;
                asm volatile("ldmatrix.sync.aligned.m8n8.x4.shared.b16 {%0,%1,%2,%3}, [%4];"
                             : "=r"(af[mb][0]), "=r"(af[mb][1]), "=r"(af[mb][2]), "=r"(af[mb][3])
                             : "r"(addr));
            }
            #pragma unroll
            for (int p = 0; p < 2; p++) {
                uint32_t addr = bbuf + boff[p] + ks * 32;
                asm volatile("ldmatrix.sync.aligned.m8n8.x4.shared.b16 {%0,%1,%2,%3}, [%4];"
                             : "=r"(bfr[2 * p][0]), "=r"(bfr[2 * p][1]),
                               "=r"(bfr[2 * p + 1][0]), "=r"(bfr[2 * p + 1][1])
                             : "r"(addr));
            }
            #pragma unroll
            for (int mb = 0; mb < 4; mb++)
                #pragma unroll
                for (int nb = 0; nb < 4; nb++) {
                    asm volatile(
                        "mma.sync.aligned.m16n8k16.row.col.f32.bf16.bf16.f32 "
                        "{%0,%1,%2,%3}, {%4,%5,%6,%7}, {%8,%9}, {%0,%1,%2,%3};"
                        : "+f"(acc[mb][nb][0]), "+f"(acc[mb][nb][1]),
                          "+f"(acc[mb][nb][2]), "+f"(acc[mb][nb][3])
                        : "r"(af[mb][0]), "r"(af[mb][1]), "r"(af[mb][2]), "r"(af[mb][3]),
                          "r"(bfr[nb][0]), "r"(bfr[nb][1]));
                }
        }

        __syncthreads();
        if (kc + 2 < NKC) load_tiles((kc + 2) * GBK, which);
        asm volatile("cp.async.commit_group;" ::: "memory");
    }

    const int g  = lane >> 2;
    const int tc = (lane & 3) * 2;
    #pragma unroll
    for (int mb = 0; mb < 4; mb++) {
        const int row0 = bm + wm * 64 + mb * 16 + g;
        #pragma unroll
        for (int nb = 0; nb < 4; nb++) {
            const int col = bn + wn * 32 + nb * 8 + tc;
            *(float2*)&C[(size_t)row0 * N + col]       = make_float2(acc[mb][nb][0], acc[mb][nb][1]);
            *(float2*)&C[(size_t)(row0 + 8) * N + col] = make_float2(acc[mb][nb][2], acc[mb][nb][3]);
        }
    }
}

// ---------------------------------------------------------------------------
// RoPE + split-bf16 expansion for Q/K
// ---------------------------------------------------------------------------
__global__ void rope_expand(const float* __restrict__ src, __nv_bfloat16* __restrict__ dst,
                            const float* __restrict__ cosb, const float* __restrict__ sinb,
                            int NH, int modeB)
{
    const int s = blockIdx.x;
    const int h = threadIdx.x >> 5;
    const int d = threadIdx.x & 31;
    const float* p = src + ((size_t)s * NH + h) * HDIM;
    const float c  = cosb[s * HDIM + d];
    const float sn = sinb[s * HDIM + d];
    const float a = p[d], b = p[d + 32];
    const float v0 = a * c - b * sn;
    const float v1 = b * c + a * sn;

    __nv_bfloat16 h0 = __float2bfloat16(v0);
    __nv_bfloat16 l0 = __float2bfloat16(v0 - __bfloat162float(h0));
    __nv_bfloat16 h1 = __float2bfloat16(v1);
    __nv_bfloat16 l1 = __float2bfloat16(v1 - __bfloat162float(h1));

    __nv_bfloat16* o = dst + ((size_t)s * NH + h) * DEXP;
    if (modeB) {
        o[d] = h0; o[64 + d] = l0; o[128 + d] = h0;
        o[d + 32] = h1; o[96 + d] = l1; o[160 + d] = h1;
    } else {
        o[d] = h0; o[64 + d] = h0; o[128 + d] = l0;
        o[d + 32] = h1; o[96 + d] = h1; o[160 + d] = l1;
    }
}

// ---------------------------------------------------------------------------
// V transpose + split: fp32 [S,KVH,64] -> bf16 [kvh][kb][d=64][vh(64)|vl(64)]
// grid (NKB_TOT, KVH), 256 threads; smem transpose, all accesses coalesced.
// ---------------------------------------------------------------------------
__global__ void v_expand(const float* __restrict__ V, __nv_bfloat16* __restrict__ vte)
{
    __shared__ float ts[64][65];
    const int kb  = blockIdx.x;
    const int kvh = blockIdx.y;
    const int tid = threadIdx.x;

    #pragma unroll
    for (int i = 0; i < 16; i++) {
        int idx = tid + 256 * i;       // 0..4095
        int s = idx >> 6, d = idx & 63;
        ts[s][d] = V[((size_t)(kb * 64 + s) * KVH + kvh) * HDIM + d];
    }
    __syncthreads();

    __nv_bfloat16* out = vte + ((size_t)(kvh * NKB_TOT + kb) * 64) * 128;
    #pragma unroll
    for (int i = 0; i < 16; i++) {
        int idx = tid + 256 * i;
        int d = idx >> 6, s = idx & 63;
        float fv = ts[s][d];
        __nv_bfloat16 vh = __float2bfloat16(fv);
        __nv_bfloat16 vl = __float2bfloat16(fv - __bfloat162float(vh));
        out[d * 128 + s]      = vh;
        out[d * 128 + 64 + s] = vl;
    }
}

// ---------------------------------------------------------------------------
// Flash attention v2: Q in registers, K/V double-buffered cp.async pipeline.
// Qe [S,H,192], Ke [S,KVH,192], Vte pre-split/transposed.
// Output: split-bf16 expanded rows into atte [S, 3*E].
// 128 threads (4 warps x 16 q-rows), BQ=64, BKT=64.
// ---------------------------------------------------------------------------
#define ROWQ 400                       // K/Q smem row stride (192 bf16 + pad)
#define ROWV 272                       // V smem row stride (128 bf16 + pad)
#define KB0_OFF 0
#define KB1_OFF (64 * ROWQ)            // 25600
#define VB0_OFF (2 * 64 * ROWQ)        // 51200
#define VB1_OFF (VB0_OFF + 64 * ROWV)  // 68608
#define ATTN_SMEM (VB1_OFF + 64 * ROWV)  // 86016

__global__ __launch_bounds__(128) void attn_mma(
    const __nv_bfloat16* __restrict__ Qe, const __nv_bfloat16* __restrict__ Ke,
    const __nv_bfloat16* __restrict__ Vte, __nv_bfloat16* __restrict__ atte)
{
    extern __shared__ __align__(16) uint8_t sm[];
    const uint32_t sb = smem_u32(sm);

    const int qb  = (int)gridDim.x - 1 - blockIdx.x;   // heavy blocks first
    const int h   = blockIdx.y;
    const int kvh = h >> 2;

    const int tid  = threadIdx.x;
    const int lane = tid & 31;
    const int w    = tid >> 5;

    const int l7  = lane & 7;
    const int l8  = (lane >> 3) & 1;
    const int l16 = (lane >> 4) & 1;
    const int g   = lane >> 2;
    const int t4  = lane & 3;

    // per-lane ldmatrix offsets (relative to buffer base)
    const uint32_t qrel = (uint32_t)(w * 16 + l7 + l8 * 8) * ROWQ + l16 * 16;
    const uint32_t krel = (uint32_t)(l7 + l16 * 8) * ROWQ + l8 * 16;
    const uint32_t vrel = (uint32_t)(l7 + l16 * 8) * ROWV + l8 * 16;

    // ---- stage Q into KB0, move to registers ----
    #pragma unroll
    for (int i = 0; i < 12; i++) {
        int idx = tid + 128 * i;
        int r = idx / 24, c = idx % 24;
        uint32_t dst = sb + KB0_OFF + r * ROWQ + c * 16;
        const __nv_bfloat16* src = Qe + ((size_t)(qb * 64 + r) * HEADS + h) * DEXP + c * 8;
        asm volatile("cp.async.cg.shared.global [%0], [%1], 16;" :: "r"(dst), "l"(src) : "memory");
    }
    asm volatile("cp.async.commit_group;" ::: "memory");
    asm volatile("cp.async.wait_group 0;" ::: "memory");
    __syncthreads();

    uint32_t qf[12][4];
    #pragma unroll
    for (int ks = 0; ks < 12; ks++) {
        asm volatile("ldmatrix.sync.aligned.m8n8.x4.shared.b16 {%0,%1,%2,%3}, [%4];"
                     : "=r"(qf[ks][0]), "=r"(qf[ks][1]), "=r"(qf[ks][2]), "=r"(qf[ks][3])
                     : "r"(sb + KB0_OFF + qrel + ks * 32));
    }
    __syncthreads();   // everyone done reading Q before KB0 is overwritten

    const int nkb = qb + 1;

    // tile loaders
    auto load_k = [&](int kb_, uint32_t buf) {
        #pragma unroll
        for (int i = 0; i < 12; i++) {
            int idx = tid + 128 * i;
            int r = idx / 24, c = idx % 24;
            uint32_t dst = sb + buf + r * ROWQ + c * 16;
            const __nv_bfloat16* src = Ke + ((size_t)(kb_ * 64 + r) * KVH + kvh) * DEXP + c * 8;
            asm volatile("cp.async.cg.shared.global [%0], [%1], 16;" :: "r"(dst), "l"(src) : "memory");
        }
    };
    auto load_v = [&](int kb_, uint32_t buf) {
        const __nv_bfloat16* base = Vte + ((size_t)(kvh * NKB_TOT + kb_) * 64) * 128;
        #pragma unroll
        for (int i = 0; i < 8; i++) {
            int idx = tid + 128 * i;     // 0..1023
            int r = idx >> 4;            // d-row 0..63
            int c = idx & 15;            // 16B chunk
            uint32_t dst = sb + buf + r * ROWV + c * 16;
            asm volatile("cp.async.cg.shared.global [%0], [%1], 16;"
                         :: "r"(dst), "l"(base + r * 128 + c * 8) : "memory");
        }
    };

    // prologue: both buffers (kb=1 addresses always valid: keys 64..127 < S)
    load_k(0, KB0_OFF); load_v(0, VB0_OFF);
    asm volatile("cp.async.commit_group;" ::: "memory");
    load_k(1, KB1_OFF); load_v(1, VB1_OFF);
    asm volatile("cp.async.commit_group;" ::: "memory");

    float m0 = -1e30f, m1 = -1e30f, l0 = 0.f, l1 = 0.f;
    float oacc[8][4];
    #pragma unroll
    for (int t = 0; t < 8; t++)
        #pragma unroll
        for (int j = 0; j < 4; j++) oacc[t][j] = 0.f;

    const float sc2 = 0.125f * 1.4426950408889634f;  // scale * log2(e)
    const int row_g0 = qb * 64 + w * 16 + g;
    const int row_g1 = row_g0 + 8;

    for (int kb = 0; kb < nkb; kb++) {
        asm volatile("cp.async.wait_group 1;" ::: "memory");
        __syncthreads();

        const uint32_t kbuf = (kb & 1) ? KB1_OFF : KB0_OFF;
        const uint32_t vbuf = (kb & 1) ? VB1_OFF : VB0_OFF;
        const uint32_t koff = sb + kbuf + krel;
        const uint32_t voff = sb + vbuf + vrel;

        // ---- QK ----
        float sacc[8][4];
        #pragma unroll
        for (int t = 0; t < 8; t++)
            #pragma unroll
            for (int j = 0; j < 4; j++) sacc[t][j] = 0.f;

        #pragma unroll
        for (int ks = 0; ks < 12; ks++) {
            uint32_t bq[8][2];
            #pragma unroll
            for (int p = 0; p < 4; p++) {
                asm volatile("ldmatrix.sync.aligned.m8n8.x4.shared.b16 {%0,%1,%2,%3}, [%4];"
                             : "=r"(bq[2 * p][0]), "=r"(bq[2 * p][1]),
                               "=r"(bq[2 * p + 1][0]), "=r"(bq[2 * p + 1][1])
                             : "r"(koff + p * 16 * ROWQ + ks * 32));
            }
            #pragma unroll
            for (int t = 0; t < 8; t++) {
                asm volatile(
                    "mma.sync.aligned.m16n8k16.row.col.f32.bf16.bf16.f32 "
                    "{%0,%1,%2,%3}, {%4,%5,%6,%7}, {%8,%9}, {%0,%1,%2,%3};"
                    : "+f"(sacc[t][0]), "+f"(sacc[t][1]), "+f"(sacc[t][2]), "+f"(sacc[t][3])
                    : "r"(qf[ks][0]), "r"(qf[ks][1]), "r"(qf[ks][2]), "r"(qf[ks][3]),
                      "r"(bq[t][0]), "r"(bq[t][1]));
            }
        }

        // ---- scale (log2 domain) + causal mask ----
        #pragma unroll
        for (int t = 0; t < 8; t++) {
            const int c0 = kb * 64 + t * 8 + 2 * t4;
            sacc[t][0] = (c0     <= row_g0) ? sacc[t][0] * sc2 : -1e30f;
            sacc[t][1] = (c0 + 1 <= row_g0) ? sacc[t][1] * sc2 : -1e30f;
            sacc[t][2] = (c0     <= row_g1) ? sacc[t][2] * sc2 : -1e30f;
            sacc[t][3] = (c0 + 1 <= row_g1) ? sacc[t][3] * sc2 : -1e30f;
        }

        // ---- online softmax (base-2) ----
        float rm0 = -1e30f, rm1 = -1e30f;
        #pragma unroll
        for (int t = 0; t < 8; t++) {
            rm0 = fmaxf(rm0, fmaxf(sacc[t][0], sacc[t][1]));
            rm1 = fmaxf(rm1, fmaxf(sacc[t][2], sacc[t][3]));
        }
        #pragma unroll
        for (int off = 1; off <= 2; off <<= 1) {
            rm0 = fmaxf(rm0, __shfl_xor_sync(0xffffffffu, rm0, off));
            rm1 = fmaxf(rm1, __shfl_xor_sync(0xffffffffu, rm1, off));
        }
        const float mn0 = fmaxf(m0, rm0), mn1 = fmaxf(m1, rm1);
        const float al0 = ex2f(m0 - mn0), al1 = ex2f(m1 - mn1);
        m0 = mn0; m1 = mn1;

        float rs0 = 0.f, rs1 = 0.f;
        #pragma unroll
        for (int t = 0; t < 8; t++) {
            sacc[t][0] = ex2f(sacc[t][0] - mn0);
            sacc[t][1] = ex2f(sacc[t][1] - mn0);
            sacc[t][2] = ex2f(sacc[t][2] - mn1);
            sacc[t][3] = ex2f(sacc[t][3] - mn1);
            rs0 += sacc[t][0] + sacc[t][1];
            rs1 += sacc[t][2] + sacc[t][3];
        }
        #pragma unroll
        for (int off = 1; off <= 2; off <<= 1) {
            rs0 += __shfl_xor_sync(0xffffffffu, rs0, off);
            rs1 += __shfl_xor_sync(0xffffffffu, rs1, off);
        }
        l0 = l0 * al0 + rs0;
        l1 = l1 * al1 + rs1;

        #pragma unroll
        for (int t = 0; t < 8; t++) {
            oacc[t][0] *= al0; oacc[t][1] *= al0;
            oacc[t][2] *= al1; oacc[t][3] *= al1;
        }

        // ---- PV (split precision): O += Ph*Vh + Pl*Vh + Ph*Vl ----
        #pragma unroll
        for (int kk = 0; kk < 4; kk++) {
            const float s00 = sacc[2 * kk][0],     s01 = sacc[2 * kk][1];
            const float s02 = sacc[2 * kk][2],     s03 = sacc[2 * kk][3];
            const float s10 = sacc[2 * kk + 1][0], s11 = sacc[2 * kk + 1][1];
            const float s12 = sacc[2 * kk + 1][2], s13 = sacc[2 * kk + 1][3];
            __nv_bfloat16 h00 = __float2bfloat16(s00), h01 = __float2bfloat16(s01);
            __nv_bfloat16 h02 = __float2bfloat16(s02), h03 = __float2bfloat16(s03);
            __nv_bfloat16 h10 = __float2bfloat16(s10), h11 = __float2bfloat16(s11);
            __nv_bfloat16 h12 = __float2bfloat16(s12), h13 = __float2bfloat16(s13);
            uint32_t pa0 = pack_bf16x2(__bfloat162float(h00), __bfloat162float(h01));
            uint32_t pa1 = pack_bf16x2(__bfloat162float(h02), __bfloat162float(h03));
            uint32_t pa2 = pack_bf16x2(__bfloat162float(h10), __bfloat162float(h11));
            uint32_t pa3 = pack_bf16x2(__bfloat162float(h12), __bfloat162float(h13));
            uint32_t la0 = pack_bf16x2(s00 - __bfloat162float(h00), s01 - __bfloat162float(h01));
            uint32_t la1 = pack_bf16x2(s02 - __bfloat162float(h02), s03 - __bfloat162float(h03));
            uint32_t la2 = pack_bf16x2(s10 - __bfloat162float(h10), s11 - __bfloat162float(h11));
            uint32_t la3 = pack_bf16x2(s12 - __bfloat162float(h12), s13 - __bfloat162float(h13));

            uint32_t bv[8][2];
            #pragma unroll
            for (int p = 0; p < 4; p++) {
                asm volatile("ldmatrix.sync.aligned.m8n8.x4.shared.b16 {%0,%1,%2,%3}, [%4];"
                             : "=r"(bv[2 * p][0]), "=r"(bv[2 * p][1]),
                               "=r"(bv[2 * p + 1][0]), "=r"(bv[2 * p + 1][1])
                             : "r"(voff + p * 16 * ROWV + kk * 32));
            }
            #pragma unroll
            for (int t = 0; t < 8; t++) {
                asm volatile(
                    "mma.sync.aligned.m16n8k16.row.col.f32.bf16.bf16.f32 "
                    "{%0,%1,%2,%3}, {%4,%5,%6,%7}, {%8,%9}, {%0,%1,%2,%3};"
                    : "+f"(oacc[t][0]), "+f"(oacc[t][1]), "+f"(oacc[t][2]), "+f"(oacc[t][3])
                    : "r"(pa0), "r"(pa1), "r"(pa2), "r"(pa3), "r"(bv[t][0]), "r"(bv[t][1]));
            }
            #pragma unroll
            for (int t = 0; t < 8; t++) {
                asm volatile(
                    "mma.sync.aligned.m16n8k16.row.col.f32.bf16.bf16.f32 "
                    "{%0,%1,%2,%3}, {%4,%5,%6,%7}, {%8,%9}, {%0,%1,%2,%3};"
                    : "+f"(oacc[t][0]), "+f"(oacc[t][1]), "+f"(oacc[t][2]), "+f"(oacc[t][3])
                    : "r"(la0), "r"(la1), "r"(la2), "r"(la3), "r"(bv[t][0]), "r"(bv[t][1]));
            }
            #pragma unroll
            for (int p = 0; p < 4; p++) {
                asm volatile("ldmatrix.sync.aligned.m8n8.x4.shared.b16 {%0,%1,%2,%3}, [%4];"
                             : "=r"(bv[2 * p][0]), "=r"(bv[2 * p][1]),
                               "=r"(bv[2 * p + 1][0]), "=r"(bv[2 * p + 1][1])
                             : "r"(voff + p * 16 * ROWV + 128 + kk * 32));
            }
            #pragma unroll
            for (int t = 0; t < 8; t++) {
                asm volatile(
                    "mma.sync.aligned.m16n8k16.row.col.f32.bf16.bf16.f32 "
                    "{%0,%1,%2,%3}, {%4,%5,%6,%7}, {%8,%9}, {%0,%1,%2,%3};"
                    : "+f"(oacc[t][0]), "+f"(oacc[t][1]), "+f"(oacc[t][2]), "+f"(oacc[t][3])
                    : "r"(pa0), "r"(pa1), "r"(pa2), "r"(pa3), "r"(bv[t][0]), "r"(bv[t][1]));
            }
        }

        __syncthreads();
        if (kb + 2 < nkb) {
            const uint32_t kbuf2 = (kb & 1) ? KB1_OFF : KB0_OFF;
            const uint32_t vbuf2 = (kb & 1) ? VB1_OFF : VB0_OFF;
            load_k(kb + 2, kbuf2);
            load_v(kb + 2, vbuf2);
        }
        asm volatile("cp.async.commit_group;" ::: "memory");
    }

    // ---- epilogue: normalize + split-bf16 expand into atte ----
    const float inv0 = 1.0f / l0;
    const float inv1 = 1.0f / l1;
    #pragma unroll
    for (int t = 0; t < 8; t++) {
        const int col = h * HDIM + t * 8 + 2 * t4;
        {
            float v0 = oacc[t][0] * inv0, v1 = oacc[t][1] * inv0;
            __nv_bfloat16 h0 = __float2bfloat16(v0), h1 = __float2bfloat16(v1);
            uint32_t hp = pack_bf16x2(__bfloat162float(h0), __bfloat162float(h1));
            uint32_t lp = pack_bf16x2(v0 - __bfloat162float(h0), v1 - __bfloat162float(h1));
            __nv_bfloat16* o = atte + (size_t)row_g0 * KEXP;
            *(uint32_t*)(o + col)              = hp;
            *(uint32_t*)(o + E_DIM + col)      = hp;
            *(uint32_t*)(o + 2 * E_DIM + col)  = lp;
        }
        {
            float v0 = oacc[t][2] * inv1, v1 = oacc[t][3] * inv1;
            __nv_bfloat16 h0 = __float2bfloat16(v0), h1 = __float2bfloat16(v1);
            uint32_t hp = pack_bf16x2(__bfloat162float(h0), __bfloat162float(h1));
            uint32_t lp = pack_bf16x2(v0 - __bfloat162float(h0), v1 - __bfloat162float(h1));
            __nv_bfloat16* o = atte + (size_t)row_g1 * KEXP;
            *(uint32_t*)(o + col)              = hp;
            *(uint32_t*)(o + E_DIM + col)      = hp;
            *(uint32_t*)(o + 2 * E_DIM + col)  = lp;
        }
    }
}

// ---------------------------------------------------------------------------
// Launch. Inputs: 0:x 1:Wq 2:Wk 3:Wv 4:Wo 5:cos 6:sin 7:attn_mask 8:last_pos
// ---------------------------------------------------------------------------
extern "C" void kernel_launch(void* const* d_in, const int* in_sizes, int n_in,
                              void* d_out, int out_size)
{
    const float* x    = (const float*)d_in[0];
    const float* Wq   = (const float*)d_in[1];
    const float* Wk   = (const float*)d_in[2];
    const float* Wv   = (const float*)d_in[3];
    const float* Wo   = (const float*)d_in[4];
    const float* cosb = (const float*)d_in[5];
    const float* sinb = (const float*)d_in[6];
    float* out = (float*)d_out;

    float *q, *k, *v;
    __nv_bfloat16 *xe, *wqe, *wke, *wve, *woe, *atte, *qe, *ke, *vte;
    cudaGetSymbolAddress((void**)&q,    g_q);
    cudaGetSymbolAddress((void**)&k,    g_k);
    cudaGetSymbolAddress((void**)&v,    g_v);
    cudaGetSymbolAddress((void**)&xe,   g_xexp);
    cudaGetSymbolAddress((void**)&wqe,  g_wqexp);
    cudaGetSymbolAddress((void**)&wke,  g_wkexp);
    cudaGetSymbolAddress((void**)&wve,  g_wvexp);
    cudaGetSymbolAddress((void**)&woe,  g_woexp);
    cudaGetSymbolAddress((void**)&atte, g_attexp);
    cudaGetSymbolAddress((void**)&qe,   g_qe);
    cudaGetSymbolAddress((void**)&ke,   g_ke);
    cudaGetSymbolAddress((void**)&vte,  g_vte);

    cudaFuncSetAttribute(attn_mma, cudaFuncAttributeMaxDynamicSharedMemorySize, ATTN_SMEM);

    // Split-bf16 expansion of GEMM operands
    split_bf16<<<4096, 256>>>(x,  xe,  S_LEN,  E_DIM, 0);
    split_bf16<<<4096, 256>>>(Wq, wqe, E_DIM,  E_DIM, 1);
    split_bf16<<<1024, 256>>>(Wk, wke, KV_DIM, E_DIM, 1);
    split_bf16<<<1024, 256>>>(Wv, wve, KV_DIM, E_DIM, 1);
    split_bf16<<<4096, 256>>>(Wo, woe, E_DIM,  E_DIM, 1);

    // QKV projections (HMMA)
    mma_gemm<<<dim3(E_DIM / 128,  S_LEN / 128), 256>>>(xe, wqe, q, S_LEN, E_DIM,  KEXP);
    mma_gemm<<<dim3(KV_DIM / 128, S_LEN / 128), 256>>>(xe, wke, k, S_LEN, KV_DIM, KEXP);
    mma_gemm<<<dim3(KV_DIM / 128, S_LEN / 128), 256>>>(xe, wve, v, S_LEN, KV_DIM, KEXP);

    // RoPE + expand Q/K; V transpose+split
    rope_expand<<<S_LEN, HEADS * 32>>>(q, qe, cosb, sinb, HEADS, 0);
    rope_expand<<<S_LEN, KVH * 32>>>(k, ke, cosb, sinb, KVH, 1);
    v_expand<<<dim3(NKB_TOT, KVH), 256>>>(v, vte);

    // Flash attention (pipelined, split precision)
    attn_mma<<<dim3(S_LEN / 64, HEADS), 128, ATTN_SMEM>>>(qe, ke, vte, atte);

    // Output projection (HMMA)
    mma_gemm<<<dim3(E_DIM / 128, S_LEN / 128), 256>>>(atte, woe, out, S_LEN, E_DIM, KEXP);
}

// round 12
// speedup vs baseline: 1.7381x; 1.0520x over previous
#include <cuda_runtime.h>
#include <cuda_bf16.h>
#include <cstdint>
#include <math.h>

// Problem constants (B=1, S=2048, E=2048, D=64, H=32, KVH=8, group=4)
#define S_LEN 2048
#define E_DIM 2048
#define HEADS 32
#define KVH 8
#define HDIM 64
#define KV_DIM (KVH * HDIM)   // 512
#define KEXP (3 * E_DIM)      // 6144 : split-bf16 expanded K
#define DEXP (3 * HDIM)       // 192  : split-bf16 expanded head dim
#define NKB_TOT (S_LEN / 64)  // 32 key blocks

// ---------------------------------------------------------------------------
// Scratch (device globals: runtime allocation is forbidden)
// ---------------------------------------------------------------------------
__device__ float g_q[S_LEN * E_DIM];
__device__ float g_k[S_LEN * KV_DIM];
__device__ float g_v[S_LEN * KV_DIM];

__device__ __nv_bfloat16 g_xexp[S_LEN * KEXP];
__device__ __nv_bfloat16 g_wqexp[E_DIM * KEXP];
__device__ __nv_bfloat16 g_wkexp[KV_DIM * KEXP];
__device__ __nv_bfloat16 g_wvexp[KV_DIM * KEXP];
__device__ __nv_bfloat16 g_woexp[E_DIM * KEXP];
__device__ __nv_bfloat16 g_attexp[S_LEN * KEXP];

__device__ __nv_bfloat16 g_qe[S_LEN * HEADS * DEXP];
__device__ __nv_bfloat16 g_ke[S_LEN * KVH * DEXP];
// V transposed + split: [kvh][kb][d=64][key: vh(0..63) | vl(64..127)]
__device__ __nv_bfloat16 g_vte[KVH * NKB_TOT * 64 * 128];

__device__ __forceinline__ uint32_t smem_u32(const void* p) {
    uint32_t a;
    asm("{ .reg .u64 t; cvta.to.shared.u64 t, %1; cvt.u32.u64 %0, t; }"
        : "=r"(a) : "l"(p));
    return a;
}

__device__ __forceinline__ uint32_t pack_bf16x2(float lo, float hi) {
    __nv_bfloat162 t = __floats2bfloat162_rn(lo, hi);
    return *reinterpret_cast<uint32_t*>(&t);
}

__device__ __forceinline__ float ex2f(float x) {
    float y;
    asm("ex2.approx.f32 %0, %1;" : "=f"(y) : "f"(x));
    return y;
}

// ---------------------------------------------------------------------------
// split-bf16 expansion: fp32 [rows,K] -> bf16 [rows,3K]
// ---------------------------------------------------------------------------
__global__ void split_bf16(const float* __restrict__ in, __nv_bfloat16* __restrict__ out,
                           int rows, int K, int modeB)
{
    int n = rows * K;
    for (int idx = blockIdx.x * blockDim.x + threadIdx.x; idx < n;
         idx += gridDim.x * blockDim.x) {
        int r = idx / K, k = idx - r * K;
        float v = in[idx];
        __nv_bfloat16 h = __float2bfloat16(v);
        __nv_bfloat16 l = __float2bfloat16(v - __bfloat162float(h));
        __nv_bfloat16* o = out + (size_t)r * (3 * K);
        if (modeB) { o[k] = h; o[K + k] = l; o[2 * K + k] = h; }
        else       { o[k] = h; o[K + k] = h; o[2 * K + k] = l; }
    }
}

// ---------------------------------------------------------------------------
// bf16 GEMM via mma.sync (unchanged, validated)
// ---------------------------------------------------------------------------
#define GBK 32
#define ROWB 80
#define TILEB (128 * ROWB)

__global__ __launch_bounds__(256) void mma_gemm(
    const __nv_bfloat16* __restrict__ A, const __nv_bfloat16* __restrict__ B,
    float* __restrict__ C, int M, int N, int K)
{
    __shared__ __align__(16) uint8_t sm[4 * TILEB];
    const uint32_t sb = smem_u32(sm);

    const int tid  = threadIdx.x;
    const int lane = tid & 31;
    const int wid  = tid >> 5;
    const int wm   = wid & 1;
    const int wn   = wid >> 1;
    const int bm   = blockIdx.y * 128;
    const int bn   = blockIdx.x * 128;

    float acc[4][4][4];
    #pragma unroll
    for (int i = 0; i < 4; i++)
        #pragma unroll
        for (int j = 0; j < 4; j++)
            #pragma unroll
            for (int c = 0; c < 4; c++) acc[i][j][c] = 0.f;

    uint32_t aoff[4], boff[2];
    {
        const int l7 = lane & 7;
        const int rA = ((lane >> 3) & 1) * 8;
        const int kA = ((lane >> 4) & 1) * 16;
        #pragma unroll
        for (int mb = 0; mb < 4; mb++)
            aoff[mb] = (uint32_t)((wm * 64 + mb * 16 + l7 + rA) * ROWB + kA);
        const int rB = ((lane >> 4) & 1) * 8;
        const int kB = ((lane >> 3) & 1) * 16;
        #pragma unroll
        for (int p = 0; p < 2; p++)
            boff[p] = (uint32_t)((wn * 32 + p * 16 + l7 + rB) * ROWB + kB);
    }

    const int NKC = K / GBK;

    auto load_tiles = [&](int k0, int which) {
        uint32_t da = sb + which * TILEB;
        uint32_t db = sb + (2 + which) * TILEB;
        #pragma unroll
        for (int i = 0; i < 2; i++) {
            int c  = tid + 256 * i;
            int r  = c >> 2;
            int cc = c & 3;
            uint32_t dsta = da + r * ROWB + cc * 16;
            uint32_t dstb = db + r * ROWB + cc * 16;
            const __nv_bfloat16* sa  = A + (size_t)(bm + r) * K + k0 + cc * 8;
            const __nv_bfloat16* sbp = B + (size_t)(bn + r) * K + k0 + cc * 8;
            asm volatile("cp.async.cg.shared.global [%0], [%1], 16;" :: "r"(dsta), "l"(sa) : "memory");
            asm volatile("cp.async.cg.shared.global [%0], [%1], 16;" :: "r"(dstb), "l"(sbp) : "memory");
        }
    };

    load_tiles(0, 0);
    asm volatile("cp.async.commit_group;" ::: "memory");
    load_tiles(GBK, 1);
    asm volatile("cp.async.commit_group;" ::: "memory");

    for (int kc = 0; kc < NKC; kc++) {
        asm volatile("cp.async.wait_group 1;" ::: "memory");
        __syncthreads();

        const int which = kc & 1;
        const uint32_t abuf = sb + which * TILEB;
        const uint32_t bbuf = sb + (2 + which) * TILEB;

        #pragma unroll
        for (int ks = 0; ks < 2; ks++) {
            uint32_t af[4][4], bfr[4][2];
            #pragma unroll
            for (int mb = 0; mb < 4; mb++) {
                uint32_t addr = abuf + aoff[mb] + ks * 32;
                asm volatile("ldmatrix.sync.aligned.m8n8.x4.shared.b16 {%0,%1,%2,%3}, [%4];"
                             : "=r"(af[mb][0]), "=r"(af[mb][1]), "=r"(af[mb][2]), "=r"(af[mb][3])
                             : "r"(addr));
            }
            #pragma unroll
            for (int p = 0; p < 2; p++) {
                uint32_t addr = bbuf + boff[p] + ks * 32;
                asm volatile("ldmatrix.sync.aligned.m8n8.x4.shared.b16 {%0,%1,%2,%3}, [%4];"
                             : "=r"(bfr[2 * p][0]), "=r"(bfr[2 * p][1]),
                               "=r"(bfr[2 * p + 1][0]), "=r"(bfr[2 * p + 1][1])
                             : "r"(addr));
            }
            #pragma unroll
            for (int mb = 0; mb < 4; mb++)
                #pragma unroll
                for (int nb = 0; nb < 4; nb++) {
                    asm volatile(
                        "mma.sync.aligned.m16n8k16.row.col.f32.bf16.bf16.f32 "
                        "{%0,%1,%2,%3}, {%4,%5,%6,%7}, {%8,%9}, {%0,%1,%2,%3};"
                        : "+f"(acc[mb][nb][0]), "+f"(acc[mb][nb][1]),
                          "+f"(acc[mb][nb][2]), "+f"(acc[mb][nb][3])
                        : "r"(af[mb][0]), "r"(af[mb][1]), "r"(af[mb][2]), "r"(af[mb][3]),
                          "r"(bfr[nb][0]), "r"(bfr[nb][1]));
                }
        }

        __syncthreads();
        if (kc + 2 < NKC) load_tiles((kc + 2) * GBK, which);
        asm volatile("cp.async.commit_group;" ::: "memory");
    }

    const int g  = lane >> 2;
    const int tc = (lane & 3) * 2;
    #pragma unroll
    for (int mb = 0; mb < 4; mb++) {
        const int row0 = bm + wm * 64 + mb * 16 + g;
        #pragma unroll
        for (int nb = 0; nb < 4; nb++) {
            const int col = bn + wn * 32 + nb * 8 + tc;
            *(float2*)&C[(size_t)row0 * N + col]       = make_float2(acc[mb][nb][0], acc[mb][nb][1]);
            *(float2*)&C[(size_t)(row0 + 8) * N + col] = make_float2(acc[mb][nb][2], acc[mb][nb][3]);
        }
    }
}

// ---------------------------------------------------------------------------
// RoPE + split-bf16 expansion for Q/K
// ---------------------------------------------------------------------------
__global__ void rope_expand(const float* __restrict__ src, __nv_bfloat16* __restrict__ dst,
                            const float* __restrict__ cosb, const float* __restrict__ sinb,
                            int NH, int modeB)
{
    const int s = blockIdx.x;
    const int h = threadIdx.x >> 5;
    const int d = threadIdx.x & 31;
    const float* p = src + ((size_t)s * NH + h) * HDIM;
    const float c  = cosb[s * HDIM + d];
    const float sn = sinb[s * HDIM + d];
    const float a = p[d], b = p[d + 32];
    const float v0 = a * c - b * sn;
    const float v1 = b * c + a * sn;

    __nv_bfloat16 h0 = __float2bfloat16(v0);
    __nv_bfloat16 l0 = __float2bfloat16(v0 - __bfloat162float(h0));
    __nv_bfloat16 h1 = __float2bfloat16(v1);
    __nv_bfloat16 l1 = __float2bfloat16(v1 - __bfloat162float(h1));

    __nv_bfloat16* o = dst + ((size_t)s * NH + h) * DEXP;
    if (modeB) {
        o[d] = h0; o[64 + d] = l0; o[128 + d] = h0;
        o[d + 32] = h1; o[96 + d] = l1; o[160 + d] = h1;
    } else {
        o[d] = h0; o[64 + d] = h0; o[128 + d] = l0;
        o[d + 32] = h1; o[96 + d] = h1; o[160 + d] = l1;
    }
}

// ---------------------------------------------------------------------------
// V transpose + split: fp32 [S,KVH,64] -> bf16 [kvh][kb][d=64][vh(64)|vl(64)]
// ---------------------------------------------------------------------------
__global__ void v_expand(const float* __restrict__ V, __nv_bfloat16* __restrict__ vte)
{
    __shared__ float ts[64][65];
    const int kb  = blockIdx.x;
    const int kvh = blockIdx.y;
    const int tid = threadIdx.x;

    #pragma unroll
    for (int i = 0; i < 16; i++) {
        int idx = tid + 256 * i;
        int s = idx >> 6, d = idx & 63;
        ts[s][d] = V[((size_t)(kb * 64 + s) * KVH + kvh) * HDIM + d];
    }
    __syncthreads();

    __nv_bfloat16* out = vte + ((size_t)(kvh * NKB_TOT + kb) * 64) * 128;
    #pragma unroll
    for (int i = 0; i < 16; i++) {
        int idx = tid + 256 * i;
        int d = idx >> 6, s = idx & 63;
        float fv = ts[s][d];
        __nv_bfloat16 vh = __float2bfloat16(fv);
        __nv_bfloat16 vl = __float2bfloat16(fv - __bfloat162float(vh));
        out[d * 128 + s]      = vh;
        out[d * 128 + 64 + s] = vl;
    }
}

// ---------------------------------------------------------------------------
// Flash attention v3: BQ=128, 8 warps, 3-stage K/V cp.async ring.
// Qe [S,H,192], Ke [S,KVH,192], Vte pre-split/transposed.
// Output: split-bf16 expanded rows into atte [S, 3*E].
// ---------------------------------------------------------------------------
#define ROWQ 400                       // K/Q smem row stride (192 bf16 + pad)
#define ROWV 272                       // V smem row stride (128 bf16 + pad)
#define KSTG (64 * ROWQ)               // 25600
#define VSTG (64 * ROWV)               // 17408
#define STAGE (KSTG + VSTG)            // 43008
#define ATTN_SMEM (3 * STAGE)          // 129024

__global__ __launch_bounds__(256, 1) void attn_mma(
    const __nv_bfloat16* __restrict__ Qe, const __nv_bfloat16* __restrict__ Ke,
    const __nv_bfloat16* __restrict__ Vte, __nv_bfloat16* __restrict__ atte)
{
    extern __shared__ __align__(16) uint8_t sm[];
    const uint32_t sb = smem_u32(sm);

    const int qb  = (int)gridDim.x - 1 - blockIdx.x;   // heavy blocks first
    const int h   = blockIdx.y;
    const int kvh = h >> 2;

    const int tid  = threadIdx.x;
    const int lane = tid & 31;
    const int w    = tid >> 5;        // 0..7, warp w owns q rows w*16..w*16+15

    const int l7  = lane & 7;
    const int l8  = (lane >> 3) & 1;
    const int l16 = (lane >> 4) & 1;
    const int g   = lane >> 2;
    const int t4  = lane & 3;

    const uint32_t qrel = (uint32_t)(w * 16 + l7 + l8 * 8) * ROWQ + l16 * 16;
    const uint32_t krel = (uint32_t)(l7 + l16 * 8) * ROWQ + l8 * 16;
    const uint32_t vrel = (uint32_t)(l7 + l16 * 8) * ROWV + l8 * 16;

    // ---- stage Q (128 rows x 192) into smem [0, 51200), move to registers ----
    #pragma unroll
    for (int i = 0; i < 12; i++) {
        int idx = tid + 256 * i;                 // 0..3071
        int r = idx / 24, c = idx % 24;
        uint32_t dst = sb + r * ROWQ + c * 16;
        const __nv_bfloat16* src = Qe + ((size_t)(qb * 128 + r) * HEADS + h) * DEXP + c * 8;
        asm volatile("cp.async.cg.shared.global [%0], [%1], 16;" :: "r"(dst), "l"(src) : "memory");
    }
    asm volatile("cp.async.commit_group;" ::: "memory");
    asm volatile("cp.async.wait_group 0;" ::: "memory");
    __syncthreads();

    uint32_t qf[12][4];
    #pragma unroll
    for (int ks = 0; ks < 12; ks++) {
        asm volatile("ldmatrix.sync.aligned.m8n8.x4.shared.b16 {%0,%1,%2,%3}, [%4];"
                     : "=r"(qf[ks][0]), "=r"(qf[ks][1]), "=r"(qf[ks][2]), "=r"(qf[ks][3])
                     : "r"(sb + qrel + ks * 32));
    }
    __syncthreads();   // all warps done reading Q before buffers are reused

    const int nkb = 2 * qb + 2;

    auto load_k = [&](int kb_, int s) {
        #pragma unroll
        for (int i = 0; i < 6; i++) {
            int idx = tid + 256 * i;             // 0..1535
            int r = idx / 24, c = idx % 24;
            uint32_t dst = sb + s * STAGE + r * ROWQ + c * 16;
            const __nv_bfloat16* src = Ke + ((size_t)(kb_ * 64 + r) * KVH + kvh) * DEXP + c * 8;
            asm volatile("cp.async.cg.shared.global [%0], [%1], 16;" :: "r"(dst), "l"(src) : "memory");
        }
    };
    auto load_v = [&](int kb_, int s) {
        const __nv_bfloat16* base = Vte + ((size_t)(kvh * NKB_TOT + kb_) * 64) * 128;
        #pragma unroll
        for (int i = 0; i < 4; i++) {
            int idx = tid + 256 * i;             // 0..1023
            int r = idx >> 4;
            int c = idx & 15;
            uint32_t dst = sb + s * STAGE + KSTG + r * ROWV + c * 16;
            asm volatile("cp.async.cg.shared.global [%0], [%1], 16;"
                         :: "r"(dst), "l"(base + r * 128 + c * 8) : "memory");
        }
    };

    // prologue (nkb >= 2 always)
    load_k(0, 0); load_v(0, 0);
    asm volatile("cp.async.commit_group;" ::: "memory");
    load_k(1, 1); load_v(1, 1);
    asm volatile("cp.async.commit_group;" ::: "memory");

    float m0 = -1e30f, m1 = -1e30f, l0 = 0.f, l1 = 0.f;
    float oacc[8][4];
    #pragma unroll
    for (int t = 0; t < 8; t++)
        #pragma unroll
        for (int j = 0; j < 4; j++) oacc[t][j] = 0.f;

    const float sc2 = 0.125f * 1.4426950408889634f;  // scale * log2(e)
    const int row_g0 = qb * 128 + w * 16 + g;
    const int row_g1 = row_g0 + 8;

    for (int kb = 0; kb < nkb; kb++) {
        asm volatile("cp.async.wait_group 1;" ::: "memory");
        __syncthreads();

        // prefetch kb+2 into the free ring slot, immediately
        if (kb + 2 < nkb) {
            int s2 = (kb + 2) % 3;
            load_k(kb + 2, s2);
            load_v(kb + 2, s2);
        }
        asm volatile("cp.async.commit_group;" ::: "memory");

        const int s = kb % 3;
        const uint32_t koff = sb + s * STAGE + krel;
        const uint32_t voff = sb + s * STAGE + KSTG + vrel;

        // ---- QK ----
        float sacc[8][4];
        #pragma unroll
        for (int t = 0; t < 8; t++)
            #pragma unroll
            for (int j = 0; j < 4; j++) sacc[t][j] = 0.f;

        #pragma unroll
        for (int ks = 0; ks < 12; ks++) {
            uint32_t bq[8][2];
            #pragma unroll
            for (int p = 0; p < 4; p++) {
                asm volatile("ldmatrix.sync.aligned.m8n8.x4.shared.b16 {%0,%1,%2,%3}, [%4];"
                             : "=r"(bq[2 * p][0]), "=r"(bq[2 * p][1]),
                               "=r"(bq[2 * p + 1][0]), "=r"(bq[2 * p + 1][1])
                             : "r"(koff + p * 16 * ROWQ + ks * 32));
            }
            #pragma unroll
            for (int t = 0; t < 8; t++) {
                asm volatile(
                    "mma.sync.aligned.m16n8k16.row.col.f32.bf16.bf16.f32 "
                    "{%0,%1,%2,%3}, {%4,%5,%6,%7}, {%8,%9}, {%0,%1,%2,%3};"
                    : "+f"(sacc[t][0]), "+f"(sacc[t][1]), "+f"(sacc[t][2]), "+f"(sacc[t][3])
                    : "r"(qf[ks][0]), "r"(qf[ks][1]), "r"(qf[ks][2]), "r"(qf[ks][3]),
                      "r"(bq[t][0]), "r"(bq[t][1]));
            }
        }

        // ---- scale (log2 domain) + causal mask ----
        #pragma unroll
        for (int t = 0; t < 8; t++) {
            const int c0 = kb * 64 + t * 8 + 2 * t4;
            sacc[t][0] = (c0     <= row_g0) ? sacc[t][0] * sc2 : -1e30f;
            sacc[t][1] = (c0 + 1 <= row_g0) ? sacc[t][1] * sc2 : -1e30f;
            sacc[t][2] = (c0     <= row_g1) ? sacc[t][2] * sc2 : -1e30f;
            sacc[t][3] = (c0 + 1 <= row_g1) ? sacc[t][3] * sc2 : -1e30f;
        }

        // ---- online softmax (base-2) ----
        float rm0 = -1e30f, rm1 = -1e30f;
        #pragma unroll
        for (int t = 0; t < 8; t++) {
            rm0 = fmaxf(rm0, fmaxf(sacc[t][0], sacc[t][1]));
            rm1 = fmaxf(rm1, fmaxf(sacc[t][2], sacc[t][3]));
        }
        #pragma unroll
        for (int off = 1; off <= 2; off <<= 1) {
            rm0 = fmaxf(rm0, __shfl_xor_sync(0xffffffffu, rm0, off));
            rm1 = fmaxf(rm1, __shfl_xor_sync(0xffffffffu, rm1, off));
        }
        const float mn0 = fmaxf(m0, rm0), mn1 = fmaxf(m1, rm1);
        const float al0 = ex2f(m0 - mn0), al1 = ex2f(m1 - mn1);
        m0 = mn0; m1 = mn1;

        float rs0 = 0.f, rs1 = 0.f;
        #pragma unroll
        for (int t = 0; t < 8; t++) {
            sacc[t][0] = ex2f(sacc[t][0] - mn0);
            sacc[t][1] = ex2f(sacc[t][1] - mn0);
            sacc[t][2] = ex2f(sacc[t][2] - mn1);
            sacc[t][3] = ex2f(sacc[t][3] - mn1);
            rs0 += sacc[t][0] + sacc[t][1];
            rs1 += sacc[t][2] + sacc[t][3];
        }
        #pragma unroll
        for (int off = 1; off <= 2; off <<= 1) {
            rs0 += __shfl_xor_sync(0xffffffffu, rs0, off);
            rs1 += __shfl_xor_sync(0xffffffffu, rs1, off);
        }
        l0 = l0 * al0 + rs0;
        l1 = l1 * al1 + rs1;

        #pragma unroll
        for (int t = 0; t < 8; t++) {
            oacc[t][0] *= al0; oacc[t][1] *= al0;
            oacc[t][2] *= al1; oacc[t][3] *= al1;
        }

        // ---- PV (split precision): O += Ph*Vh + Pl*Vh + Ph*Vl ----
        #pragma unroll
        for (int kk = 0; kk < 4; kk++) {
            const float s00 = sacc[2 * kk][0],     s01 = sacc[2 * kk][1];
            const float s02 = sacc[2 * kk][2],     s03 = sacc[2 * kk][3];
            const float s10 = sacc[2 * kk + 1][0], s11 = sacc[2 * kk + 1][1];
            const float s12 = sacc[2 * kk + 1][2], s13 = sacc[2 * kk + 1][3];
            __nv_bfloat16 h00 = __float2bfloat16(s00), h01 = __float2bfloat16(s01);
            __nv_bfloat16 h02 = __float2bfloat16(s02), h03 = __float2bfloat16(s03);
            __nv_bfloat16 h10 = __float2bfloat16(s10), h11 = __float2bfloat16(s11);
            __nv_bfloat16 h12 = __float2bfloat16(s12), h13 = __float2bfloat16(s13);
            uint32_t pa0 = pack_bf16x2(__bfloat162float(h00), __bfloat162float(h01));
            uint32_t pa1 = pack_bf16x2(__bfloat162float(h02), __bfloat162float(h03));
            uint32_t pa2 = pack_bf16x2(__bfloat162float(h10), __bfloat162float(h11));
            uint32_t pa3 = pack_bf16x2(__bfloat162float(h12), __bfloat162float(h13));
            uint32_t la0 = pack_bf16x2(s00 - __bfloat162float(h00), s01 - __bfloat162float(h01));
            uint32_t la1 = pack_bf16x2(s02 - __bfloat162float(h02), s03 - __bfloat162float(h03));
            uint32_t la2 = pack_bf16x2(s10 - __bfloat162float(h10), s11 - __bfloat162float(h11));
            uint32_t la3 = pack_bf16x2(s12 - __bfloat162float(h12), s13 - __bfloat162float(h13));

            uint32_t bv[8][2];
            #pragma unroll
            for (int p = 0; p < 4; p++) {
                asm volatile("ldmatrix.sync.aligned.m8n8.x4.shared.b16 {%0,%1,%2,%3}, [%4];"
                             : "=r"(bv[2 * p][0]), "=r"(bv[2 * p][1]),
                               "=r"(bv[2 * p + 1][0]), "=r"(bv[2 * p + 1][1])
                             : "r"(voff + p * 16 * ROWV + kk * 32));
            }
            #pragma unroll
            for (int t = 0; t < 8; t++) {
                asm volatile(
                    "mma.sync.aligned.m16n8k16.row.col.f32.bf16.bf16.f32 "
                    "{%0,%1,%2,%3}, {%4,%5,%6,%7}, {%8,%9}, {%0,%1,%2,%3};"
                    : "+f"(oacc[t][0]), "+f"(oacc[t][1]), "+f"(oacc[t][2]), "+f"(oacc[t][3])
                    : "r"(pa0), "r"(pa1), "r"(pa2), "r"(pa3), "r"(bv[t][0]), "r"(bv[t][1]));
            }
            #pragma unroll
            for (int t = 0; t < 8; t++) {
                asm volatile(
                    "mma.sync.aligned.m16n8k16.row.col.f32.bf16.bf16.f32 "
                    "{%0,%1,%2,%3}, {%4,%5,%6,%7}, {%8,%9}, {%0,%1,%2,%3};"
                    : "+f"(oacc[t][0]), "+f"(oacc[t][1]), "+f"(oacc[t][2]), "+f"(oacc[t][3])
                    : "r"(la0), "r"(la1), "r"(la2), "r"(la3), "r"(bv[t][0]), "r"(bv[t][1]));
            }
            #pragma unroll
            for (int p = 0; p < 4; p++) {
                asm volatile("ldmatrix.sync.aligned.m8n8.x4.shared.b16 {%0,%1,%2,%3}, [%4];"
                             : "=r"(bv[2 * p][0]), "=r"(bv[2 * p][1]),
                               "=r"(bv[2 * p + 1][0]), "=r"(bv[2 * p + 1][1])
                             : "r"(voff + p * 16 * ROWV + 128 + kk * 32));
            }
            #pragma unroll
            for (int t = 0; t < 8; t++) {
                asm volatile(
                    "mma.sync.aligned.m16n8k16.row.col.f32.bf16.bf16.f32 "
                    "{%0,%1,%2,%3}, {%4,%5,%6,%7}, {%8,%9}, {%0,%1,%2,%3};"
                    : "+f"(oacc[t][0]), "+f"(oacc[t][1]), "+f"(oacc[t][2]), "+f"(oacc[t][3])
                    : "r"(pa0), "r"(pa1), "r"(pa2), "r"(pa3), "r"(bv[t][0]), "r"(bv[t][1]));
            }
        }
    }

    // ---- epilogue: normalize + split-bf16 expand into atte ----
    const float inv0 = 1.0f / l0;
    const float inv1 = 1.0f / l1;
    #pragma unroll
    for (int t = 0; t < 8; t++) {
        const int col = h * HDIM + t * 8 + 2 * t4;
        {
            float v0 = oacc[t][0] * inv0, v1 = oacc[t][1] * inv0;
            __nv_bfloat16 h0 = __float2bfloat16(v0), h1 = __float2bfloat16(v1);
            uint32_t hp = pack_bf16x2(__bfloat162float(h0), __bfloat162float(h1));
            uint32_t lp = pack_bf16x2(v0 - __bfloat162float(h0), v1 - __bfloat162float(h1));
            __nv_bfloat16* o = atte + (size_t)row_g0 * KEXP;
            *(uint32_t*)(o + col)              = hp;
            *(uint32_t*)(o + E_DIM + col)      = hp;
            *(uint32_t*)(o + 2 * E_DIM + col)  = lp;
        }
        {
            float v0 = oacc[t][2] * inv1, v1 = oacc[t][3] * inv1;
            __nv_bfloat16 h0 = __float2bfloat16(v0), h1 = __float2bfloat16(v1);
            uint32_t hp = pack_bf16x2(__bfloat162float(h0), __bfloat162float(h1));
            uint32_t lp = pack_bf16x2(v0 - __bfloat162float(h0), v1 - __bfloat162float(h1));
            __nv_bfloat16* o = atte + (size_t)row_g1 * KEXP;
            *(uint32_t*)(o + col)              = hp;
            *(uint32_t*)(o + E_DIM + col)      = hp;
            *(uint32_t*)(o + 2 * E_DIM + col)  = lp;
        }
    }
}

// ---------------------------------------------------------------------------
// Launch. Inputs: 0:x 1:Wq 2:Wk 3:Wv 4:Wo 5:cos 6:sin 7:attn_mask 8:last_pos
// ---------------------------------------------------------------------------
extern "C" void kernel_launch(void* const* d_in, const int* in_sizes, int n_in,
                              void* d_out, int out_size)
{
    const float* x    = (const float*)d_in[0];
    const float* Wq   = (const float*)d_in[1];
    const float* Wk   = (const float*)d_in[2];
    const float* Wv   = (const float*)d_in[3];
    const float* Wo   = (const float*)d_in[4];
    const float* cosb = (const float*)d_in[5];
    const float* sinb = (const float*)d_in[6];
    float* out = (float*)d_out;

    float *q, *k, *v;
    __nv_bfloat16 *xe, *wqe, *wke, *wve, *woe, *atte, *qe, *ke, *vte;
    cudaGetSymbolAddress((void**)&q,    g_q);
    cudaGetSymbolAddress((void**)&k,    g_k);
    cudaGetSymbolAddress((void**)&v,    g_v);
    cudaGetSymbolAddress((void**)&xe,   g_xexp);
    cudaGetSymbolAddress((void**)&wqe,  g_wqexp);
    cudaGetSymbolAddress((void**)&wke,  g_wkexp);
    cudaGetSymbolAddress((void**)&wve,  g_wvexp);
    cudaGetSymbolAddress((void**)&woe,  g_woexp);
    cudaGetSymbolAddress((void**)&atte, g_attexp);
    cudaGetSymbolAddress((void**)&qe,   g_qe);
    cudaGetSymbolAddress((void**)&ke,   g_ke);
    cudaGetSymbolAddress((void**)&vte,  g_vte);

    cudaFuncSetAttribute(attn_mma, cudaFuncAttributeMaxDynamicSharedMemorySize, ATTN_SMEM);

    // Split-bf16 expansion of GEMM operands
    split_bf16<<<4096, 256>>>(x,  xe,  S_LEN,  E_DIM, 0);
    split_bf16<<<4096, 256>>>(Wq, wqe, E_DIM,  E_DIM, 1);
    split_bf16<<<1024, 256>>>(Wk, wke, KV_DIM, E_DIM, 1);
    split_bf16<<<1024, 256>>>(Wv, wve, KV_DIM, E_DIM, 1);
    split_bf16<<<4096, 256>>>(Wo, woe, E_DIM,  E_DIM, 1);

    // QKV projections (HMMA)
    mma_gemm<<<dim3(E_DIM / 128,  S_LEN / 128), 256>>>(xe, wqe, q, S_LEN, E_DIM,  KEXP);
    mma_gemm<<<dim3(KV_DIM / 128, S_LEN / 128), 256>>>(xe, wke, k, S_LEN, KV_DIM, KEXP);
    mma_gemm<<<dim3(KV_DIM / 128, S_LEN / 128), 256>>>(xe, wve, v, S_LEN, KV_DIM, KEXP);

    // RoPE + expand Q/K; V transpose+split
    rope_expand<<<S_LEN, HEADS * 32>>>(q, qe, cosb, sinb, HEADS, 0);
    rope_expand<<<S_LEN, KVH * 32>>>(k, ke, cosb, sinb, KVH, 1);
    v_expand<<<dim3(NKB_TOT, KVH), 256>>>(v, vte);

    // Flash attention (BQ=128, 8 warps, 3-stage ring)
    attn_mma<<<dim3(S_LEN / 128, HEADS), 256, ATTN_SMEM>>>(qe, ke, vte, atte);

    // Output projection (HMMA)
    mma_gemm<<<dim3(E_DIM / 128, S_LEN / 128), 256>>>(atte, woe, out, S_LEN, E_DIM, KEXP);
}

// round 13
// speedup vs baseline: 2.6676x; 1.5348x over previous
#include <cuda_runtime.h>
#include <cuda_bf16.h>
#include <cuda_fp16.h>
#include <cstdint>
#include <math.h>

// Problem constants (B=1, S=2048, E=2048, D=64, H=32, KVH=8, group=4)
#define S_LEN 2048
#define E_DIM 2048
#define HEADS 32
#define KVH 8
#define HDIM 64
#define KV_DIM (KVH * HDIM)   // 512
#define NQKV (E_DIM + 2 * KV_DIM)  // 3072 fused QKV output width
#define KEXP (3 * E_DIM)      // 6144 : split-bf16 expanded K
#define DEXP (3 * HDIM)       // 192  : split-bf16 expanded head dim
#define NKB_TOT (S_LEN / 64)  // 32 key blocks

// ---------------------------------------------------------------------------
// Scratch (device globals: runtime allocation is forbidden)
// ---------------------------------------------------------------------------
__device__ float g_qkv[S_LEN * NQKV];                 // fused QKV fp32

__device__ __nv_bfloat16 g_xexp[S_LEN * KEXP];
__device__ __nv_bfloat16 g_wqkve[NQKV * KEXP];        // Wq|Wk|Wv expanded
__device__ __nv_bfloat16 g_qe[S_LEN * HEADS * DEXP];  // rope'd Q, expanded
__device__ __nv_bfloat16 g_ke[S_LEN * KVH * DEXP];    // rope'd K, expanded

__device__ __half g_vt[KVH * NKB_TOT * 64 * 64];      // V transposed fp16
__device__ __half g_attf[S_LEN * E_DIM];              // attention out fp16
__device__ __half g_wof[E_DIM * E_DIM];               // Wo fp16

__device__ __forceinline__ uint32_t smem_u32(const void* p) {
    uint32_t a;
    asm("{ .reg .u64 t; cvta.to.shared.u64 t, %1; cvt.u32.u64 %0, t; }"
        : "=r"(a) : "l"(p));
    return a;
}

__device__ __forceinline__ uint32_t pack_bf16x2(float lo, float hi) {
    __nv_bfloat162 t = __floats2bfloat162_rn(lo, hi);
    return *reinterpret_cast<uint32_t*>(&t);
}

__device__ __forceinline__ uint32_t pack_h2(float lo, float hi) {
    __half2 t = __floats2half2_rn(lo, hi);
    return *reinterpret_cast<uint32_t*>(&t);
}

__device__ __forceinline__ float ex2f(float x) {
    float y;
    asm("ex2.approx.f32 %0, %1;" : "=f"(y) : "f"(x));
    return y;
}

// ---------------------------------------------------------------------------
// split-bf16 expansion: fp32 [rows,K] -> bf16 [rows,3K]
// ---------------------------------------------------------------------------
__global__ void split_bf16(const float* __restrict__ in, __nv_bfloat16* __restrict__ out,
                           int rows, int K, int modeB)
{
    int n = rows * K;
    for (int idx = blockIdx.x * blockDim.x + threadIdx.x; idx < n;
         idx += gridDim.x * blockDim.x) {
        int r = idx / K, k = idx - r * K;
        float v = in[idx];
        __nv_bfloat16 h = __float2bfloat16(v);
        __nv_bfloat16 l = __float2bfloat16(v - __bfloat162float(h));
        __nv_bfloat16* o = out + (size_t)r * (3 * K);
        if (modeB) { o[k] = h; o[K + k] = l; o[2 * K + k] = h; }
        else       { o[k] = h; o[K + k] = h; o[2 * K + k] = l; }
    }
}

__global__ void conv_f16(const float* __restrict__ in, __half* __restrict__ out, int n)
{
    for (int i = blockIdx.x * blockDim.x + threadIdx.x; i < n; i += gridDim.x * blockDim.x)
        out[i] = __float2half(in[i]);
}

// ---------------------------------------------------------------------------
// bf16 GEMM via mma.sync (validated): C = A @ B^T
// ---------------------------------------------------------------------------
#define GBK 32
#define ROWB 80
#define TILEB (128 * ROWB)

__global__ __launch_bounds__(256) void mma_gemm(
    const __nv_bfloat16* __restrict__ A, const __nv_bfloat16* __restrict__ B,
    float* __restrict__ C, int M, int N, int K)
{
    __shared__ __align__(16) uint8_t sm[4 * TILEB];
    const uint32_t sb = smem_u32(sm);

    const int tid  = threadIdx.x;
    const int lane = tid & 31;
    const int wid  = tid >> 5;
    const int wm   = wid & 1;
    const int wn   = wid >> 1;
    const int bm   = blockIdx.y * 128;
    const int bn   = blockIdx.x * 128;

    float acc[4][4][4];
    #pragma unroll
    for (int i = 0; i < 4; i++)
        #pragma unroll
        for (int j = 0; j < 4; j++)
            #pragma unroll
            for (int c = 0; c < 4; c++) acc[i][j][c] = 0.f;

    uint32_t aoff[4], boff[2];
    {
        const int l7 = lane & 7;
        const int rA = ((lane >> 3) & 1) * 8;
        const int kA = ((lane >> 4) & 1) * 16;
        #pragma unroll
        for (int mb = 0; mb < 4; mb++)
            aoff[mb] = (uint32_t)((wm * 64 + mb * 16 + l7 + rA) * ROWB + kA);
        const int rB = ((lane >> 4) & 1) * 8;
        const int kB = ((lane >> 3) & 1) * 16;
        #pragma unroll
        for (int p = 0; p < 2; p++)
            boff[p] = (uint32_t)((wn * 32 + p * 16 + l7 + rB) * ROWB + kB);
    }

    const int NKC = K / GBK;

    auto load_tiles = [&](int k0, int which) {
        uint32_t da = sb + which * TILEB;
        uint32_t db = sb + (2 + which) * TILEB;
        #pragma unroll
        for (int i = 0; i < 2; i++) {
            int c  = tid + 256 * i;
            int r  = c >> 2;
            int cc = c & 3;
            uint32_t dsta = da + r * ROWB + cc * 16;
            uint32_t dstb = db + r * ROWB + cc * 16;
            const __nv_bfloat16* sa  = A + (size_t)(bm + r) * K + k0 + cc * 8;
            const __nv_bfloat16* sbp = B + (size_t)(bn + r) * K + k0 + cc * 8;
            asm volatile("cp.async.cg.shared.global [%0], [%1], 16;" :: "r"(dsta), "l"(sa) : "memory");
            asm volatile("cp.async.cg.shared.global [%0], [%1], 16;" :: "r"(dstb), "l"(sbp) : "memory");
        }
    };

    load_tiles(0, 0);
    asm volatile("cp.async.commit_group;" ::: "memory");
    load_tiles(GBK, 1);
    asm volatile("cp.async.commit_group;" ::: "memory");

    for (int kc = 0; kc < NKC; kc++) {
        asm volatile("cp.async.wait_group 1;" ::: "memory");
        __syncthreads();

        const int which = kc & 1;
        const uint32_t abuf = sb + which * TILEB;
        const uint32_t bbuf = sb + (2 + which) * TILEB;

        #pragma unroll
        for (int ks = 0; ks < 2; ks++) {
            uint32_t af[4][4], bfr[4][2];
            #pragma unroll
            for (int mb = 0; mb < 4; mb++) {
                asm volatile("ldmatrix.sync.aligned.m8n8.x4.shared.b16 {%0,%1,%2,%3}, [%4];"
                             : "=r"(af[mb][0]), "=r"(af[mb][1]), "=r"(af[mb][2]), "=r"(af[mb][3])
                             : "r"(abuf + aoff[mb] + ks * 32));
            }
            #pragma unroll
            for (int p = 0; p < 2; p++) {
                asm volatile("ldmatrix.sync.aligned.m8n8.x4.shared.b16 {%0,%1,%2,%3}, [%4];"
                             : "=r"(bfr[2 * p][0]), "=r"(bfr[2 * p][1]),
                               "=r"(bfr[2 * p + 1][0]), "=r"(bfr[2 * p + 1][1])
                             : "r"(bbuf + boff[p] + ks * 32));
            }
            #pragma unroll
            for (int mb = 0; mb < 4; mb++)
                #pragma unroll
                for (int nb = 0; nb < 4; nb++) {
                    asm volatile(
                        "mma.sync.aligned.m16n8k16.row.col.f32.bf16.bf16.f32 "
                        "{%0,%1,%2,%3}, {%4,%5,%6,%7}, {%8,%9}, {%0,%1,%2,%3};"
                        : "+f"(acc[mb][nb][0]), "+f"(acc[mb][nb][1]),
                          "+f"(acc[mb][nb][2]), "+f"(acc[mb][nb][3])
                        : "r"(af[mb][0]), "r"(af[mb][1]), "r"(af[mb][2]), "r"(af[mb][3]),
                          "r"(bfr[nb][0]), "r"(bfr[nb][1]));
                }
        }

        __syncthreads();
        if (kc + 2 < NKC) load_tiles((kc + 2) * GBK, which);
        asm volatile("cp.async.commit_group;" ::: "memory");
    }

    const int g  = lane >> 2;
    const int tc = (lane & 3) * 2;
    #pragma unroll
    for (int mb = 0; mb < 4; mb++) {
        const int row0 = bm + wm * 64 + mb * 16 + g;
        #pragma unroll
        for (int nb = 0; nb < 4; nb++) {
            const int col = bn + wn * 32 + nb * 8 + tc;
            *(float2*)&C[(size_t)row0 * N + col]       = make_float2(acc[mb][nb][0], acc[mb][nb][1]);
            *(float2*)&C[(size_t)(row0 + 8) * N + col] = make_float2(acc[mb][nb][2], acc[mb][nb][3]);
        }
    }
}

// ---------------------------------------------------------------------------
// fp16 GEMM via mma.sync (same structure, f16 operands): C = A @ B^T
// ---------------------------------------------------------------------------
__global__ __launch_bounds__(256) void mma_gemm_f16(
    const __half* __restrict__ A, const __half* __restrict__ B,
    float* __restrict__ C, int M, int N, int K)
{
    __shared__ __align__(16) uint8_t sm[4 * TILEB];
    const uint32_t sb = smem_u32(sm);

    const int tid  = threadIdx.x;
    const int lane = tid & 31;
    const int wid  = tid >> 5;
    const int wm   = wid & 1;
    const int wn   = wid >> 1;
    const int bm   = blockIdx.y * 128;
    const int bn   = blockIdx.x * 128;

    float acc[4][4][4];
    #pragma unroll
    for (int i = 0; i < 4; i++)
        #pragma unroll
        for (int j = 0; j < 4; j++)
            #pragma unroll
            for (int c = 0; c < 4; c++) acc[i][j][c] = 0.f;

    uint32_t aoff[4], boff[2];
    {
        const int l7 = lane & 7;
        const int rA = ((lane >> 3) & 1) * 8;
        const int kA = ((lane >> 4) & 1) * 16;
        #pragma unroll
        for (int mb = 0; mb < 4; mb++)
            aoff[mb] = (uint32_t)((wm * 64 + mb * 16 + l7 + rA) * ROWB + kA);
        const int rB = ((lane >> 4) & 1) * 8;
        const int kB = ((lane >> 3) & 1) * 16;
        #pragma unroll
        for (int p = 0; p < 2; p++)
            boff[p] = (uint32_t)((wn * 32 + p * 16 + l7 + rB) * ROWB + kB);
    }

    const int NKC = K / GBK;

    auto load_tiles = [&](int k0, int which) {
        uint32_t da = sb + which * TILEB;
        uint32_t db = sb + (2 + which) * TILEB;
        #pragma unroll
        for (int i = 0; i < 2; i++) {
            int c  = tid + 256 * i;
            int r  = c >> 2;
            int cc = c & 3;
            const __half* sa  = A + (size_t)(bm + r) * K + k0 + cc * 8;
            const __half* sbp = B + (size_t)(bn + r) * K + k0 + cc * 8;
            asm volatile("cp.async.cg.shared.global [%0], [%1], 16;"
                         :: "r"(da + r * ROWB + cc * 16), "l"(sa) : "memory");
            asm volatile("cp.async.cg.shared.global [%0], [%1], 16;"
                         :: "r"(db + r * ROWB + cc * 16), "l"(sbp) : "memory");
        }
    };

    load_tiles(0, 0);
    asm volatile("cp.async.commit_group;" ::: "memory");
    load_tiles(GBK, 1);
    asm volatile("cp.async.commit_group;" ::: "memory");

    for (int kc = 0; kc < NKC; kc++) {
        asm volatile("cp.async.wait_group 1;" ::: "memory");
        __syncthreads();

        const int which = kc & 1;
        const uint32_t abuf = sb + which * TILEB;
        const uint32_t bbuf = sb + (2 + which) * TILEB;

        #pragma unroll
        for (int ks = 0; ks < 2; ks++) {
            uint32_t af[4][4], bfr[4][2];
            #pragma unroll
            for (int mb = 0; mb < 4; mb++) {
                asm volatile("ldmatrix.sync.aligned.m8n8.x4.shared.b16 {%0,%1,%2,%3}, [%4];"
                             : "=r"(af[mb][0]), "=r"(af[mb][1]), "=r"(af[mb][2]), "=r"(af[mb][3])
                             : "r"(abuf + aoff[mb] + ks * 32));
            }
            #pragma unroll
            for (int p = 0; p < 2; p++) {
                asm volatile("ldmatrix.sync.aligned.m8n8.x4.shared.b16 {%0,%1,%2,%3}, [%4];"
                             : "=r"(bfr[2 * p][0]), "=r"(bfr[2 * p][1]),
                               "=r"(bfr[2 * p + 1][0]), "=r"(bfr[2 * p + 1][1])
                             : "r"(bbuf + boff[p] + ks * 32));
            }
            #pragma unroll
            for (int mb = 0; mb < 4; mb++)
                #pragma unroll
                for (int nb = 0; nb < 4; nb++) {
                    asm volatile(
                        "mma.sync.aligned.m16n8k16.row.col.f32.f16.f16.f32 "
                        "{%0,%1,%2,%3}, {%4,%5,%6,%7}, {%8,%9}, {%0,%1,%2,%3};"
                        : "+f"(acc[mb][nb][0]), "+f"(acc[mb][nb][1]),
                          "+f"(acc[mb][nb][2]), "+f"(acc[mb][nb][3])
                        : "r"(af[mb][0]), "r"(af[mb][1]), "r"(af[mb][2]), "r"(af[mb][3]),
                          "r"(bfr[nb][0]), "r"(bfr[nb][1]));
                }
        }

        __syncthreads();
        if (kc + 2 < NKC) load_tiles((kc + 2) * GBK, which);
        asm volatile("cp.async.commit_group;" ::: "memory");
    }

    const int g  = lane >> 2;
    const int tc = (lane & 3) * 2;
    #pragma unroll
    for (int mb = 0; mb < 4; mb++) {
        const int row0 = bm + wm * 64 + mb * 16 + g;
        #pragma unroll
        for (int nb = 0; nb < 4; nb++) {
            const int col = bn + wn * 32 + nb * 8 + tc;
            *(float2*)&C[(size_t)row0 * N + col]       = make_float2(acc[mb][nb][0], acc[mb][nb][1]);
            *(float2*)&C[(size_t)(row0 + 8) * N + col] = make_float2(acc[mb][nb][2], acc[mb][nb][3]);
        }
    }
}

// ---------------------------------------------------------------------------
// RoPE + split-bf16 expansion, reading from fused QKV buffer.
// src row = s*srcStride + h*64.  modeB=0 -> [h|h|l] (Q), 1 -> [h|l|h] (K)
// ---------------------------------------------------------------------------
__global__ void rope_expand(const float* __restrict__ src, int srcStride,
                            __nv_bfloat16* __restrict__ dst,
                            const float* __restrict__ cosb, const float* __restrict__ sinb,
                            int NH, int modeB)
{
    const int s = blockIdx.x;
    const int h = threadIdx.x >> 5;
    const int d = threadIdx.x & 31;
    const float* p = src + (size_t)s * srcStride + h * HDIM;
    const float c  = cosb[s * HDIM + d];
    const float sn = sinb[s * HDIM + d];
    const float a = p[d], b = p[d + 32];
    const float v0 = a * c - b * sn;
    const float v1 = b * c + a * sn;

    __nv_bfloat16 h0 = __float2bfloat16(v0);
    __nv_bfloat16 l0 = __float2bfloat16(v0 - __bfloat162float(h0));
    __nv_bfloat16 h1 = __float2bfloat16(v1);
    __nv_bfloat16 l1 = __float2bfloat16(v1 - __bfloat162float(h1));

    __nv_bfloat16* o = dst + ((size_t)s * NH + h) * DEXP;
    if (modeB) {
        o[d] = h0; o[64 + d] = l0; o[128 + d] = h0;
        o[d + 32] = h1; o[96 + d] = l1; o[160 + d] = h1;
    } else {
        o[d] = h0; o[64 + d] = h0; o[128 + d] = l0;
        o[d + 32] = h1; o[96 + d] = h1; o[160 + d] = l1;
    }
}

// ---------------------------------------------------------------------------
// V transpose to fp16: qkv[.., 2560 + kvh*64 + d] -> vt[kvh][kb][d=64][key=64]
// ---------------------------------------------------------------------------
__global__ void v_expand(const float* __restrict__ QKV, __half* __restrict__ vt)
{
    __shared__ float ts[64][65];
    const int kb  = blockIdx.x;
    const int kvh = blockIdx.y;
    const int tid = threadIdx.x;

    #pragma unroll
    for (int i = 0; i < 16; i++) {
        int idx = tid + 256 * i;
        int s = idx >> 6, d = idx & 63;
        ts[s][d] = QKV[(size_t)(kb * 64 + s) * NQKV + E_DIM + KV_DIM + kvh * HDIM + d];
    }
    __syncthreads();

    __half* out = vt + ((size_t)(kvh * NKB_TOT + kb) * 64) * 64;
    #pragma unroll
    for (int i = 0; i < 16; i++) {
        int idx = tid + 256 * i;
        int d = idx >> 6, s = idx & 63;
        out[d * 64 + s] = __float2half(ts[s][d]);
    }
}

// ---------------------------------------------------------------------------
// Flash attention: BQ=128, 8 warps, 3-stage K/V ring.
// QK: 3-term split-bf16 (D'=192). PV: single-pass fp16.
// Output: fp16 rows into attf [S, 2048].
// ---------------------------------------------------------------------------
#define ROWQ 400                       // K/Q smem row stride (192 bf16 + pad)
#define ROWV 144                       // V smem row stride (64 fp16 + pad)
#define KSTG (64 * ROWQ)               // 25600
#define VSTG (64 * ROWV)               // 9216
#define STAGE (KSTG + VSTG)            // 34816
#define ATTN_SMEM (3 * STAGE)          // 104448

__global__ __launch_bounds__(256, 1) void attn_mma(
    const __nv_bfloat16* __restrict__ Qe, const __nv_bfloat16* __restrict__ Ke,
    const __half* __restrict__ Vt, __half* __restrict__ attf)
{
    extern __shared__ __align__(16) uint8_t sm[];
    const uint32_t sb = smem_u32(sm);

    const int qb  = (int)gridDim.x - 1 - blockIdx.x;   // heavy blocks first
    const int h   = blockIdx.y;
    const int kvh = h >> 2;

    const int tid  = threadIdx.x;
    const int lane = tid & 31;
    const int w    = tid >> 5;

    const int l7  = lane & 7;
    const int l8  = (lane >> 3) & 1;
    const int l16 = (lane >> 4) & 1;
    const int g   = lane >> 2;
    const int t4  = lane & 3;

    const uint32_t qrel = (uint32_t)(w * 16 + l7 + l8 * 8) * ROWQ + l16 * 16;
    const uint32_t krel = (uint32_t)(l7 + l16 * 8) * ROWQ + l8 * 16;
    const uint32_t vrel = (uint32_t)(l7 + l16 * 8) * ROWV + l8 * 16;

    // ---- stage Q (128 x 192) through smem, move to registers ----
    #pragma unroll
    for (int i = 0; i < 12; i++) {
        int idx = tid + 256 * i;
        int r = idx / 24, c = idx % 24;
        uint32_t dst = sb + r * ROWQ + c * 16;
        const __nv_bfloat16* src = Qe + ((size_t)(qb * 128 + r) * HEADS + h) * DEXP + c * 8;
        asm volatile("cp.async.cg.shared.global [%0], [%1], 16;" :: "r"(dst), "l"(src) : "memory");
    }
    asm volatile("cp.async.commit_group;" ::: "memory");
    asm volatile("cp.async.wait_group 0;" ::: "memory");
    __syncthreads();

    uint32_t qf[12][4];
    #pragma unroll
    for (int ks = 0; ks < 12; ks++) {
        asm volatile("ldmatrix.sync.aligned.m8n8.x4.shared.b16 {%0,%1,%2,%3}, [%4];"
                     : "=r"(qf[ks][0]), "=r"(qf[ks][1]), "=r"(qf[ks][2]), "=r"(qf[ks][3])
                     : "r"(sb + qrel + ks * 32));
    }
    __syncthreads();

    const int nkb = 2 * qb + 2;

    auto load_k = [&](int kb_, int s) {
        #pragma unroll
        for (int i = 0; i < 6; i++) {
            int idx = tid + 256 * i;
            int r = idx / 24, c = idx % 24;
            uint32_t dst = sb + s * STAGE + r * ROWQ + c * 16;
            const __nv_bfloat16* src = Ke + ((size_t)(kb_ * 64 + r) * KVH + kvh) * DEXP + c * 8;
            asm volatile("cp.async.cg.shared.global [%0], [%1], 16;" :: "r"(dst), "l"(src) : "memory");
        }
    };
    auto load_v = [&](int kb_, int s) {
        const __half* base = Vt + ((size_t)(kvh * NKB_TOT + kb_) * 64) * 64;
        #pragma unroll
        for (int i = 0; i < 2; i++) {
            int idx = tid + 256 * i;     // 0..511
            int r = idx >> 3;            // d-row 0..63
            int c = idx & 7;             // 16B chunk
            uint32_t dst = sb + s * STAGE + KSTG + r * ROWV + c * 16;
            asm volatile("cp.async.cg.shared.global [%0], [%1], 16;"
                         :: "r"(dst), "l"(base + r * 64 + c * 8) : "memory");
        }
    };

    load_k(0, 0); load_v(0, 0);
    asm volatile("cp.async.commit_group;" ::: "memory");
    load_k(1, 1); load_v(1, 1);
    asm volatile("cp.async.commit_group;" ::: "memory");

    float m0 = -1e30f, m1 = -1e30f, l0 = 0.f, l1 = 0.f;
    float oacc[8][4];
    #pragma unroll
    for (int t = 0; t < 8; t++)
        #pragma unroll
        for (int j = 0; j < 4; j++) oacc[t][j] = 0.f;

    const float sc2 = 0.125f * 1.4426950408889634f;
    const int row_g0 = qb * 128 + w * 16 + g;
    const int row_g1 = row_g0 + 8;

    for (int kb = 0; kb < nkb; kb++) {
        asm volatile("cp.async.wait_group 1;" ::: "memory");
        __syncthreads();

        if (kb + 2 < nkb) {
            int s2 = (kb + 2) % 3;
            load_k(kb + 2, s2);
            load_v(kb + 2, s2);
        }
        asm volatile("cp.async.commit_group;" ::: "memory");

        const int s = kb % 3;
        const uint32_t koff = sb + s * STAGE + krel;
        const uint32_t voff = sb + s * STAGE + KSTG + vrel;

        // ---- QK (3-term split-bf16) ----
        float sacc[8][4];
        #pragma unroll
        for (int t = 0; t < 8; t++)
            #pragma unroll
            for (int j = 0; j < 4; j++) sacc[t][j] = 0.f;

        #pragma unroll
        for (int ks = 0; ks < 12; ks++) {
            uint32_t bq[8][2];
            #pragma unroll
            for (int p = 0; p < 4; p++) {
                asm volatile("ldmatrix.sync.aligned.m8n8.x4.shared.b16 {%0,%1,%2,%3}, [%4];"
                             : "=r"(bq[2 * p][0]), "=r"(bq[2 * p][1]),
                               "=r"(bq[2 * p + 1][0]), "=r"(bq[2 * p + 1][1])
                             : "r"(koff + p * 16 * ROWQ + ks * 32));
            }
            #pragma unroll
            for (int t = 0; t < 8; t++) {
                asm volatile(
                    "mma.sync.aligned.m16n8k16.row.col.f32.bf16.bf16.f32 "
                    "{%0,%1,%2,%3}, {%4,%5,%6,%7}, {%8,%9}, {%0,%1,%2,%3};"
                    : "+f"(sacc[t][0]), "+f"(sacc[t][1]), "+f"(sacc[t][2]), "+f"(sacc[t][3])
                    : "r"(qf[ks][0]), "r"(qf[ks][1]), "r"(qf[ks][2]), "r"(qf[ks][3]),
                      "r"(bq[t][0]), "r"(bq[t][1]));
            }
        }

        // ---- scale (log2 domain) + causal mask ----
        #pragma unroll
        for (int t = 0; t < 8; t++) {
            const int c0 = kb * 64 + t * 8 + 2 * t4;
            sacc[t][0] = (c0     <= row_g0) ? sacc[t][0] * sc2 : -1e30f;
            sacc[t][1] = (c0 + 1 <= row_g0) ? sacc[t][1] * sc2 : -1e30f;
            sacc[t][2] = (c0     <= row_g1) ? sacc[t][2] * sc2 : -1e30f;
            sacc[t][3] = (c0 + 1 <= row_g1) ? sacc[t][3] * sc2 : -1e30f;
        }

        // ---- online softmax (base-2) ----
        float rm0 = -1e30f, rm1 = -1e30f;
        #pragma unroll
        for (int t = 0; t < 8; t++) {
            rm0 = fmaxf(rm0, fmaxf(sacc[t][0], sacc[t][1]));
            rm1 = fmaxf(rm1, fmaxf(sacc[t][2], sacc[t][3]));
        }
        #pragma unroll
        for (int off = 1; off <= 2; off <<= 1) {
            rm0 = fmaxf(rm0, __shfl_xor_sync(0xffffffffu, rm0, off));
            rm1 = fmaxf(rm1, __shfl_xor_sync(0xffffffffu, rm1, off));
        }
        const float mn0 = fmaxf(m0, rm0), mn1 = fmaxf(m1, rm1);
        const float al0 = ex2f(m0 - mn0), al1 = ex2f(m1 - mn1);
        m0 = mn0; m1 = mn1;

        float rs0 = 0.f, rs1 = 0.f;
        #pragma unroll
        for (int t = 0; t < 8; t++) {
            sacc[t][0] = ex2f(sacc[t][0] - mn0);
            sacc[t][1] = ex2f(sacc[t][1] - mn0);
            sacc[t][2] = ex2f(sacc[t][2] - mn1);
            sacc[t][3] = ex2f(sacc[t][3] - mn1);
            rs0 += sacc[t][0] + sacc[t][1];
            rs1 += sacc[t][2] + sacc[t][3];
        }
        #pragma unroll
        for (int off = 1; off <= 2; off <<= 1) {
            rs0 += __shfl_xor_sync(0xffffffffu, rs0, off);
            rs1 += __shfl_xor_sync(0xffffffffu, rs1, off);
        }
        l0 = l0 * al0 + rs0;
        l1 = l1 * al1 + rs1;

        #pragma unroll
        for (int t = 0; t < 8; t++) {
            oacc[t][0] *= al0; oacc[t][1] *= al0;
            oacc[t][2] *= al1; oacc[t][3] *= al1;
        }

        // ---- PV: single-pass fp16 ----
        #pragma unroll
        for (int kk = 0; kk < 4; kk++) {
            uint32_t pa0 = pack_h2(sacc[2 * kk][0],     sacc[2 * kk][1]);
            uint32_t pa1 = pack_h2(sacc[2 * kk][2],     sacc[2 * kk][3]);
            uint32_t pa2 = pack_h2(sacc[2 * kk + 1][0], sacc[2 * kk + 1][1]);
            uint32_t pa3 = pack_h2(sacc[2 * kk + 1][2], sacc[2 * kk + 1][3]);

            uint32_t bv[8][2];
            #pragma unroll
            for (int p = 0; p < 4; p++) {
                asm volatile("ldmatrix.sync.aligned.m8n8.x4.shared.b16 {%0,%1,%2,%3}, [%4];"
                             : "=r"(bv[2 * p][0]), "=r"(bv[2 * p][1]),
                               "=r"(bv[2 * p + 1][0]), "=r"(bv[2 * p + 1][1])
                             : "r"(voff + p * 16 * ROWV + kk * 32));
            }
            #pragma unroll
            for (int t = 0; t < 8; t++) {
                asm volatile(
                    "mma.sync.aligned.m16n8k16.row.col.f32.f16.f16.f32 "
                    "{%0,%1,%2,%3}, {%4,%5,%6,%7}, {%8,%9}, {%0,%1,%2,%3};"
                    : "+f"(oacc[t][0]), "+f"(oacc[t][1]), "+f"(oacc[t][2]), "+f"(oacc[t][3])
                    : "r"(pa0), "r"(pa1), "r"(pa2), "r"(pa3), "r"(bv[t][0]), "r"(bv[t][1]));
            }
        }
    }

    // ---- epilogue: normalize, write fp16 rows ----
    const float inv0 = 1.0f / l0;
    const float inv1 = 1.0f / l1;
    #pragma unroll
    for (int t = 0; t < 8; t++) {
        const int col = h * HDIM + t * 8 + 2 * t4;
        *(uint32_t*)(attf + (size_t)row_g0 * E_DIM + col) =
            pack_h2(oacc[t][0] * inv0, oacc[t][1] * inv0);
        *(uint32_t*)(attf + (size_t)row_g1 * E_DIM + col) =
            pack_h2(oacc[t][2] * inv1, oacc[t][3] * inv1);
    }
}

// ---------------------------------------------------------------------------
// Launch. Inputs: 0:x 1:Wq 2:Wk 3:Wv 4:Wo 5:cos 6:sin 7:attn_mask 8:last_pos
// ---------------------------------------------------------------------------
extern "C" void kernel_launch(void* const* d_in, const int* in_sizes, int n_in,
                              void* d_out, int out_size)
{
    const float* x    = (const float*)d_in[0];
    const float* Wq   = (const float*)d_in[1];
    const float* Wk   = (const float*)d_in[2];
    const float* Wv   = (const float*)d_in[3];
    const float* Wo   = (const float*)d_in[4];
    const float* cosb = (const float*)d_in[5];
    const float* sinb = (const float*)d_in[6];
    float* out = (float*)d_out;

    float* qkv;
    __nv_bfloat16 *xe, *wqkve, *qe, *ke;
    __half *vt, *attf, *wof;
    cudaGetSymbolAddress((void**)&qkv,   g_qkv);
    cudaGetSymbolAddress((void**)&xe,    g_xexp);
    cudaGetSymbolAddress((void**)&wqkve, g_wqkve);
    cudaGetSymbolAddress((void**)&qe,    g_qe);
    cudaGetSymbolAddress((void**)&ke,    g_ke);
    cudaGetSymbolAddress((void**)&vt,    g_vt);
    cudaGetSymbolAddress((void**)&attf,  g_attf);
    cudaGetSymbolAddress((void**)&wof,   g_wof);

    cudaFuncSetAttribute(attn_mma, cudaFuncAttributeMaxDynamicSharedMemorySize, ATTN_SMEM);

    // Operand prep
    split_bf16<<<4096, 256>>>(x,  xe, S_LEN, E_DIM, 0);
    split_bf16<<<4096, 256>>>(Wq, wqkve,                       E_DIM,  E_DIM, 1);
    split_bf16<<<1024, 256>>>(Wk, wqkve + (size_t)E_DIM * KEXP,            KV_DIM, E_DIM, 1);
    split_bf16<<<1024, 256>>>(Wv, wqkve + (size_t)(E_DIM + KV_DIM) * KEXP, KV_DIM, E_DIM, 1);
    conv_f16<<<2048, 256>>>(Wo, wof, E_DIM * E_DIM);

    // Fused QKV projection (bf16 3-term, one wave-efficient GEMM)
    mma_gemm<<<dim3(NQKV / 128, S_LEN / 128), 256>>>(xe, wqkve, qkv, S_LEN, NQKV, KEXP);

    // RoPE + expand Q/K; V transpose to fp16
    rope_expand<<<S_LEN, HEADS * 32>>>(qkv,          NQKV, qe, cosb, sinb, HEADS, 0);
    rope_expand<<<S_LEN, KVH * 32>>>(qkv + E_DIM,    NQKV, ke, cosb, sinb, KVH, 1);
    v_expand<<<dim3(NKB_TOT, KVH), 256>>>(qkv, vt);

    // Flash attention
    attn_mma<<<dim3(S_LEN / 128, HEADS), 256, ATTN_SMEM>>>(qe, ke, vt, attf);

    // Output projection (fp16 single-term)
    mma_gemm_f16<<<dim3(E_DIM / 128, S_LEN / 128), 256>>>(attf, wof, out, S_LEN, E_DIM, E_DIM);
}

// round 14
// speedup vs baseline: 4.7606x; 1.7846x over previous
#include <cuda_runtime.h>
#include <cuda_bf16.h>
#include <cuda_fp16.h>
#include <cstdint>
#include <math.h>

// Problem constants (B=1, S=2048, E=2048, D=64, H=32, KVH=8, group=4)
#define S_LEN 2048
#define E_DIM 2048
#define HEADS 32
#define KVH 8
#define HDIM 64
#define KV_DIM (KVH * HDIM)        // 512
#define NQKV (E_DIM + 2 * KV_DIM)  // 3072
#define NKB_TOT (S_LEN / 64)       // 32 key blocks

// ---------------------------------------------------------------------------
// Scratch (device globals: runtime allocation is forbidden)
// ---------------------------------------------------------------------------
__device__ float  g_qkv[S_LEN * NQKV];            // fused QKV fp32
__device__ __half g_xf[S_LEN * E_DIM];            // x fp16
__device__ __half g_wqkvf[NQKV * E_DIM];          // Wq|Wk|Wv fp16
__device__ __half g_qf[S_LEN * HEADS * HDIM];     // rope'd Q fp16
__device__ __half g_kf[S_LEN * KVH * HDIM];       // rope'd K fp16
__device__ __half g_vt[KVH * NKB_TOT * 64 * 64];  // V transposed fp16
__device__ __half g_attf[S_LEN * E_DIM];          // attention out fp16
__device__ __half g_wof[E_DIM * E_DIM];           // Wo fp16

__device__ __forceinline__ uint32_t smem_u32(const void* p) {
    uint32_t a;
    asm("{ .reg .u64 t; cvta.to.shared.u64 t, %1; cvt.u32.u64 %0, t; }"
        : "=r"(a) : "l"(p));
    return a;
}

__device__ __forceinline__ uint32_t pack_h2(float lo, float hi) {
    __half2 t = __floats2half2_rn(lo, hi);
    return *reinterpret_cast<uint32_t*>(&t);
}

__device__ __forceinline__ float ex2f(float x) {
    float y;
    asm("ex2.approx.f32 %0, %1;" : "=f"(y) : "f"(x));
    return y;
}

__global__ void conv_f16(const float* __restrict__ in, __half* __restrict__ out, int n)
{
    for (int i = blockIdx.x * blockDim.x + threadIdx.x; i < n; i += gridDim.x * blockDim.x)
        out[i] = __float2half(in[i]);
}

// ---------------------------------------------------------------------------
// fp16 GEMM via mma.sync: C[M,N] fp32 = A[M,K] @ B[N,K]^T
// 128x128 tile, BK=32, 8 warps, cp.async double buffer.
// ---------------------------------------------------------------------------
#define GBK 32
#define ROWB 80
#define TILEB (128 * ROWB)

__global__ __launch_bounds__(256) void mma_gemm_f16(
    const __half* __restrict__ A, const __half* __restrict__ B,
    float* __restrict__ C, int M, int N, int K)
{
    __shared__ __align__(16) uint8_t sm[4 * TILEB];
    const uint32_t sb = smem_u32(sm);

    const int tid  = threadIdx.x;
    const int lane = tid & 31;
    const int wid  = tid >> 5;
    const int wm   = wid & 1;
    const int wn   = wid >> 1;
    const int bm   = blockIdx.y * 128;
    const int bn   = blockIdx.x * 128;

    float acc[4][4][4];
    #pragma unroll
    for (int i = 0; i < 4; i++)
        #pragma unroll
        for (int j = 0; j < 4; j++)
            #pragma unroll
            for (int c = 0; c < 4; c++) acc[i][j][c] = 0.f;

    uint32_t aoff[4], boff[2];
    {
        const int l7 = lane & 7;
        const int rA = ((lane >> 3) & 1) * 8;
        const int kA = ((lane >> 4) & 1) * 16;
        #pragma unroll
        for (int mb = 0; mb < 4; mb++)
            aoff[mb] = (uint32_t)((wm * 64 + mb * 16 + l7 + rA) * ROWB + kA);
        const int rB = ((lane >> 4) & 1) * 8;
        const int kB = ((lane >> 3) & 1) * 16;
        #pragma unroll
        for (int p = 0; p < 2; p++)
            boff[p] = (uint32_t)((wn * 32 + p * 16 + l7 + rB) * ROWB + kB);
    }

    const int NKC = K / GBK;

    auto load_tiles = [&](int k0, int which) {
        uint32_t da = sb + which * TILEB;
        uint32_t db = sb + (2 + which) * TILEB;
        #pragma unroll
        for (int i = 0; i < 2; i++) {
            int c  = tid + 256 * i;
            int r  = c >> 2;
            int cc = c & 3;
            const __half* sa  = A + (size_t)(bm + r) * K + k0 + cc * 8;
            const __half* sbp = B + (size_t)(bn + r) * K + k0 + cc * 8;
            asm volatile("cp.async.cg.shared.global [%0], [%1], 16;"
                         :: "r"(da + r * ROWB + cc * 16), "l"(sa) : "memory");
            asm volatile("cp.async.cg.shared.global [%0], [%1], 16;"
                         :: "r"(db + r * ROWB + cc * 16), "l"(sbp) : "memory");
        }
    };

    load_tiles(0, 0);
    asm volatile("cp.async.commit_group;" ::: "memory");
    load_tiles(GBK, 1);
    asm volatile("cp.async.commit_group;" ::: "memory");

    for (int kc = 0; kc < NKC; kc++) {
        asm volatile("cp.async.wait_group 1;" ::: "memory");
        __syncthreads();

        const int which = kc & 1;
        const uint32_t abuf = sb + which * TILEB;
        const uint32_t bbuf = sb + (2 + which) * TILEB;

        #pragma unroll
        for (int ks = 0; ks < 2; ks++) {
            uint32_t af[4][4], bfr[4][2];
            #pragma unroll
            for (int mb = 0; mb < 4; mb++) {
                asm volatile("ldmatrix.sync.aligned.m8n8.x4.shared.b16 {%0,%1,%2,%3}, [%4];"
                             : "=r"(af[mb][0]), "=r"(af[mb][1]), "=r"(af[mb][2]), "=r"(af[mb][3])
                             : "r"(abuf + aoff[mb] + ks * 32));
            }
            #pragma unroll
            for (int p = 0; p < 2; p++) {
                asm volatile("ldmatrix.sync.aligned.m8n8.x4.shared.b16 {%0,%1,%2,%3}, [%4];"
                             : "=r"(bfr[2 * p][0]), "=r"(bfr[2 * p][1]),
                               "=r"(bfr[2 * p + 1][0]), "=r"(bfr[2 * p + 1][1])
                             : "r"(bbuf + boff[p] + ks * 32));
            }
            #pragma unroll
            for (int mb = 0; mb < 4; mb++)
                #pragma unroll
                for (int nb = 0; nb < 4; nb++) {
                    asm volatile(
                        "mma.sync.aligned.m16n8k16.row.col.f32.f16.f16.f32 "
                        "{%0,%1,%2,%3}, {%4,%5,%6,%7}, {%8,%9}, {%0,%1,%2,%3};"
                        : "+f"(acc[mb][nb][0]), "+f"(acc[mb][nb][1]),
                          "+f"(acc[mb][nb][2]), "+f"(acc[mb][nb][3])
                        : "r"(af[mb][0]), "r"(af[mb][1]), "r"(af[mb][2]), "r"(af[mb][3]),
                          "r"(bfr[nb][0]), "r"(bfr[nb][1]));
                }
        }

        __syncthreads();
        if (kc + 2 < NKC) load_tiles((kc + 2) * GBK, which);
        asm volatile("cp.async.commit_group;" ::: "memory");
    }

    const int g  = lane >> 2;
    const int tc = (lane & 3) * 2;
    #pragma unroll
    for (int mb = 0; mb < 4; mb++) {
        const int row0 = bm + wm * 64 + mb * 16 + g;
        #pragma unroll
        for (int nb = 0; nb < 4; nb++) {
            const int col = bn + wn * 32 + nb * 8 + tc;
            *(float2*)&C[(size_t)row0 * N + col]       = make_float2(acc[mb][nb][0], acc[mb][nb][1]);
            *(float2*)&C[(size_t)(row0 + 8) * N + col] = make_float2(acc[mb][nb][2], acc[mb][nb][3]);
        }
    }
}

// ---------------------------------------------------------------------------
// RoPE -> fp16. src row = s*stride + h*64.
// ---------------------------------------------------------------------------
__global__ void rope_f16(const float* __restrict__ src, int stride,
                         __half* __restrict__ dst,
                         const float* __restrict__ cosb, const float* __restrict__ sinb,
                         int NH)
{
    const int s = blockIdx.x;
    const int h = threadIdx.x >> 5;
    const int d = threadIdx.x & 31;
    const float* p = src + (size_t)s * stride + h * HDIM;
    const float c  = cosb[s * HDIM + d];
    const float sn = sinb[s * HDIM + d];
    const float a = p[d], b = p[d + 32];
    __half* o = dst + ((size_t)s * NH + h) * HDIM;
    o[d]      = __float2half(a * c - b * sn);
    o[d + 32] = __float2half(b * c + a * sn);
}

// ---------------------------------------------------------------------------
// V transpose to fp16: qkv[.., 2560 + kvh*64 + d] -> vt[kvh][kb][d=64][key=64]
// ---------------------------------------------------------------------------
__global__ void v_expand(const float* __restrict__ QKV, __half* __restrict__ vt)
{
    __shared__ float ts[64][65];
    const int kb  = blockIdx.x;
    const int kvh = blockIdx.y;
    const int tid = threadIdx.x;

    #pragma unroll
    for (int i = 0; i < 16; i++) {
        int idx = tid + 256 * i;
        int s = idx >> 6, d = idx & 63;
        ts[s][d] = QKV[(size_t)(kb * 64 + s) * NQKV + E_DIM + KV_DIM + kvh * HDIM + d];
    }
    __syncthreads();

    __half* out = vt + ((size_t)(kvh * NKB_TOT + kb) * 64) * 64;
    #pragma unroll
    for (int i = 0; i < 16; i++) {
        int idx = tid + 256 * i;
        int d = idx >> 6, s = idx & 63;
        out[d * 64 + s] = __float2half(ts[s][d]);
    }
}

// ---------------------------------------------------------------------------
// Flash attention, all-fp16 operands: BQ=128, 8 warps, 3-stage K/V ring.
// Qf [S,H,64], Kf [S,KVH,64], Vt transposed. Output fp16 into attf [S,2048].
// ---------------------------------------------------------------------------
#define ROWK 144                       // 64 fp16 = 128B + 16 pad
#define KSTG (64 * ROWK)               // 9216
#define VSTG (64 * ROWK)               // 9216
#define STAGE (KSTG + VSTG)            // 18432
#define ATTN_SMEM (3 * STAGE)          // 55296

__global__ __launch_bounds__(256, 2) void attn_mma(
    const __half* __restrict__ Qf, const __half* __restrict__ Kf,
    const __half* __restrict__ Vt, __half* __restrict__ attf)
{
    extern __shared__ __align__(16) uint8_t sm[];
    const uint32_t sb = smem_u32(sm);

    const int qb  = (int)gridDim.x - 1 - blockIdx.x;   // heavy blocks first
    const int h   = blockIdx.y;
    const int kvh = h >> 2;

    const int tid  = threadIdx.x;
    const int lane = tid & 31;
    const int w    = tid >> 5;

    const int l7  = lane & 7;
    const int l8  = (lane >> 3) & 1;
    const int l16 = (lane >> 4) & 1;
    const int g   = lane >> 2;
    const int t4  = lane & 3;

    const uint32_t qrel = (uint32_t)(w * 16 + l7 + l8 * 8) * ROWK + l16 * 16;
    const uint32_t krel = (uint32_t)(l7 + l16 * 8) * ROWK + l8 * 16;
    const uint32_t vrel = (uint32_t)(l7 + l16 * 8) * ROWK + l8 * 16;

    // ---- stage Q (128 rows x 64 fp16) through smem, move to registers ----
    #pragma unroll
    for (int i = 0; i < 4; i++) {
        int idx = tid + 256 * i;                 // 0..1023
        int r = idx >> 3, c = idx & 7;
        uint32_t dst = sb + r * ROWK + c * 16;
        const __half* src = Qf + ((size_t)(qb * 128 + r) * HEADS + h) * HDIM + c * 8;
        asm volatile("cp.async.cg.shared.global [%0], [%1], 16;" :: "r"(dst), "l"(src) : "memory");
    }
    asm volatile("cp.async.commit_group;" ::: "memory");
    asm volatile("cp.async.wait_group 0;" ::: "memory");
    __syncthreads();

    uint32_t qf[4][4];
    #pragma unroll
    for (int ks = 0; ks < 4; ks++) {
        asm volatile("ldmatrix.sync.aligned.m8n8.x4.shared.b16 {%0,%1,%2,%3}, [%4];"
                     : "=r"(qf[ks][0]), "=r"(qf[ks][1]), "=r"(qf[ks][2]), "=r"(qf[ks][3])
                     : "r"(sb + qrel + ks * 32));
    }
    __syncthreads();   // all warps done with Q before stage 0 is overwritten

    const int nkb = 2 * qb + 2;

    auto load_k = [&](int kb_, int s) {
        #pragma unroll
        for (int i = 0; i < 2; i++) {
            int idx = tid + 256 * i;             // 0..511
            int r = idx >> 3, c = idx & 7;
            uint32_t dst = sb + s * STAGE + r * ROWK + c * 16;
            const __half* src = Kf + ((size_t)(kb_ * 64 + r) * KVH + kvh) * HDIM + c * 8;
            asm volatile("cp.async.cg.shared.global [%0], [%1], 16;" :: "r"(dst), "l"(src) : "memory");
        }
    };
    auto load_v = [&](int kb_, int s) {
        const __half* base = Vt + ((size_t)(kvh * NKB_TOT + kb_) * 64) * 64;
        #pragma unroll
        for (int i = 0; i < 2; i++) {
            int idx = tid + 256 * i;             // 0..511
            int r = idx >> 3, c = idx & 7;
            uint32_t dst = sb + s * STAGE + KSTG + r * ROWK + c * 16;
            asm volatile("cp.async.cg.shared.global [%0], [%1], 16;"
                         :: "r"(dst), "l"(base + r * 64 + c * 8) : "memory");
        }
    };

    load_k(0, 0); load_v(0, 0);
    asm volatile("cp.async.commit_group;" ::: "memory");
    load_k(1, 1); load_v(1, 1);
    asm volatile("cp.async.commit_group;" ::: "memory");

    float m0 = -1e30f, m1 = -1e30f, l0 = 0.f, l1 = 0.f;
    float oacc[8][4];
    #pragma unroll
    for (int t = 0; t < 8; t++)
        #pragma unroll
        for (int j = 0; j < 4; j++) oacc[t][j] = 0.f;

    const float sc2 = 0.125f * 1.4426950408889634f;  // scale * log2(e)
    const int row_g0 = qb * 128 + w * 16 + g;
    const int row_g1 = row_g0 + 8;

    for (int kb = 0; kb < nkb; kb++) {
        asm volatile("cp.async.wait_group 1;" ::: "memory");
        __syncthreads();

        if (kb + 2 < nkb) {
            int s2 = (kb + 2) % 3;
            load_k(kb + 2, s2);
            load_v(kb + 2, s2);
        }
        asm volatile("cp.async.commit_group;" ::: "memory");

        const int s = kb % 3;
        const uint32_t koff = sb + s * STAGE + krel;
        const uint32_t voff = sb + s * STAGE + KSTG + vrel;

        // ---- QK (fp16, D=64) ----
        float sacc[8][4];
        #pragma unroll
        for (int t = 0; t < 8; t++)
            #pragma unroll
            for (int j = 0; j < 4; j++) sacc[t][j] = 0.f;

        #pragma unroll
        for (int ks = 0; ks < 4; ks++) {
            uint32_t bq[8][2];
            #pragma unroll
            for (int p = 0; p < 4; p++) {
                asm volatile("ldmatrix.sync.aligned.m8n8.x4.shared.b16 {%0,%1,%2,%3}, [%4];"
                             : "=r"(bq[2 * p][0]), "=r"(bq[2 * p][1]),
                               "=r"(bq[2 * p + 1][0]), "=r"(bq[2 * p + 1][1])
                             : "r"(koff + p * 16 * ROWK + ks * 32));
            }
            #pragma unroll
            for (int t = 0; t < 8; t++) {
                asm volatile(
                    "mma.sync.aligned.m16n8k16.row.col.f32.f16.f16.f32 "
                    "{%0,%1,%2,%3}, {%4,%5,%6,%7}, {%8,%9}, {%0,%1,%2,%3};"
                    : "+f"(sacc[t][0]), "+f"(sacc[t][1]), "+f"(sacc[t][2]), "+f"(sacc[t][3])
                    : "r"(qf[ks][0]), "r"(qf[ks][1]), "r"(qf[ks][2]), "r"(qf[ks][3]),
                      "r"(bq[t][0]), "r"(bq[t][1]));
            }
        }

        // ---- scale (log2 domain) + causal mask ----
        #pragma unroll
        for (int t = 0; t < 8; t++) {
            const int c0 = kb * 64 + t * 8 + 2 * t4;
            sacc[t][0] = (c0     <= row_g0) ? sacc[t][0] * sc2 : -1e30f;
            sacc[t][1] = (c0 + 1 <= row_g0) ? sacc[t][1] * sc2 : -1e30f;
            sacc[t][2] = (c0     <= row_g1) ? sacc[t][2] * sc2 : -1e30f;
            sacc[t][3] = (c0 + 1 <= row_g1) ? sacc[t][3] * sc2 : -1e30f;
        }

        // ---- online softmax (base-2) ----
        float rm0 = -1e30f, rm1 = -1e30f;
        #pragma unroll
        for (int t = 0; t < 8; t++) {
            rm0 = fmaxf(rm0, fmaxf(sacc[t][0], sacc[t][1]));
            rm1 = fmaxf(rm1, fmaxf(sacc[t][2], sacc[t][3]));
        }
        #pragma unroll
        for (int off = 1; off <= 2; off <<= 1) {
            rm0 = fmaxf(rm0, __shfl_xor_sync(0xffffffffu, rm0, off));
            rm1 = fmaxf(rm1, __shfl_xor_sync(0xffffffffu, rm1, off));
        }
        const float mn0 = fmaxf(m0, rm0), mn1 = fmaxf(m1, rm1);
        const float al0 = ex2f(m0 - mn0), al1 = ex2f(m1 - mn1);
        m0 = mn0; m1 = mn1;

        float rs0 = 0.f, rs1 = 0.f;
        #pragma unroll
        for (int t = 0; t < 8; t++) {
            sacc[t][0] = ex2f(sacc[t][0] - mn0);
            sacc[t][1] = ex2f(sacc[t][1] - mn0);
            sacc[t][2] = ex2f(sacc[t][2] - mn1);
            sacc[t][3] = ex2f(sacc[t][3] - mn1);
            rs0 += sacc[t][0] + sacc[t][1];
            rs1 += sacc[t][2] + sacc[t][3];
        }
        #pragma unroll
        for (int off = 1; off <= 2; off <<= 1) {
            rs0 += __shfl_xor_sync(0xffffffffu, rs0, off);
            rs1 += __shfl_xor_sync(0xffffffffu, rs1, off);
        }
        l0 = l0 * al0 + rs0;
        l1 = l1 * al1 + rs1;

        #pragma unroll
        for (int t = 0; t < 8; t++) {
            oacc[t][0] *= al0; oacc[t][1] *= al0;
            oacc[t][2] *= al1; oacc[t][3] *= al1;
        }

        // ---- PV: fp16 single pass ----
        #pragma unroll
        for (int kk = 0; kk < 4; kk++) {
            uint32_t pa0 = pack_h2(sacc[2 * kk][0],     sacc[2 * kk][1]);
            uint32_t pa1 = pack_h2(sacc[2 * kk][2],     sacc[2 * kk][3]);
            uint32_t pa2 = pack_h2(sacc[2 * kk + 1][0], sacc[2 * kk + 1][1]);
            uint32_t pa3 = pack_h2(sacc[2 * kk + 1][2], sacc[2 * kk + 1][3]);

            uint32_t bv[8][2];
            #pragma unroll
            for (int p = 0; p < 4; p++) {
                asm volatile("ldmatrix.sync.aligned.m8n8.x4.shared.b16 {%0,%1,%2,%3}, [%4];"
                             : "=r"(bv[2 * p][0]), "=r"(bv[2 * p][1]),
                               "=r"(bv[2 * p + 1][0]), "=r"(bv[2 * p + 1][1])
                             : "r"(voff + p * 16 * ROWK + kk * 32));
            }
            #pragma unroll
            for (int t = 0; t < 8; t++) {
                asm volatile(
                    "mma.sync.aligned.m16n8k16.row.col.f32.f16.f16.f32 "
                    "{%0,%1,%2,%3}, {%4,%5,%6,%7}, {%8,%9}, {%0,%1,%2,%3};"
                    : "+f"(oacc[t][0]), "+f"(oacc[t][1]), "+f"(oacc[t][2]), "+f"(oacc[t][3])
                    : "r"(pa0), "r"(pa1), "r"(pa2), "r"(pa3), "r"(bv[t][0]), "r"(bv[t][1]));
            }
        }
    }

    // ---- epilogue: normalize, write fp16 rows ----
    const float inv0 = 1.0f / l0;
    const float inv1 = 1.0f / l1;
    #pragma unroll
    for (int t = 0; t < 8; t++) {
        const int col = h * HDIM + t * 8 + 2 * t4;
        *(uint32_t*)(attf + (size_t)row_g0 * E_DIM + col) =
            pack_h2(oacc[t][0] * inv0, oacc[t][1] * inv0);
        *(uint32_t*)(attf + (size_t)row_g1 * E_DIM + col) =
            pack_h2(oacc[t][2] * inv1, oacc[t][3] * inv1);
    }
}

// ---------------------------------------------------------------------------
// Launch. Inputs: 0:x 1:Wq 2:Wk 3:Wv 4:Wo 5:cos 6:sin 7:attn_mask 8:last_pos
// ---------------------------------------------------------------------------
extern "C" void kernel_launch(void* const* d_in, const int* in_sizes, int n_in,
                              void* d_out, int out_size)
{
    const float* x    = (const float*)d_in[0];
    const float* Wq   = (const float*)d_in[1];
    const float* Wk   = (const float*)d_in[2];
    const float* Wv   = (const float*)d_in[3];
    const float* Wo   = (const float*)d_in[4];
    const float* cosb = (const float*)d_in[5];
    const float* sinb = (const float*)d_in[6];
    float* out = (float*)d_out;

    float* qkv;
    __half *xf, *wqkvf, *qf, *kf, *vt, *attf, *wof;
    cudaGetSymbolAddress((void**)&qkv,   g_qkv);
    cudaGetSymbolAddress((void**)&xf,    g_xf);
    cudaGetSymbolAddress((void**)&wqkvf, g_wqkvf);
    cudaGetSymbolAddress((void**)&qf,    g_qf);
    cudaGetSymbolAddress((void**)&kf,    g_kf);
    cudaGetSymbolAddress((void**)&vt,    g_vt);
    cudaGetSymbolAddress((void**)&attf,  g_attf);
    cudaGetSymbolAddress((void**)&wof,   g_wof);

    cudaFuncSetAttribute(attn_mma, cudaFuncAttributeMaxDynamicSharedMemorySize, ATTN_SMEM);

    // fp16 operand prep
    conv_f16<<<2048, 256>>>(x,  xf, S_LEN * E_DIM);
    conv_f16<<<2048, 256>>>(Wq, wqkvf,                              E_DIM * E_DIM);
    conv_f16<<<512,  256>>>(Wk, wqkvf + (size_t)E_DIM * E_DIM,      KV_DIM * E_DIM);
    conv_f16<<<512,  256>>>(Wv, wqkvf + (size_t)(E_DIM + KV_DIM) * E_DIM, KV_DIM * E_DIM);
    conv_f16<<<2048, 256>>>(Wo, wof, E_DIM * E_DIM);

    // Fused QKV projection (fp16, K=2048)
    mma_gemm_f16<<<dim3(NQKV / 128, S_LEN / 128), 256>>>(xf, wqkvf, qkv, S_LEN, NQKV, E_DIM);

    // RoPE -> fp16 Q/K; V transpose to fp16
    rope_f16<<<S_LEN, HEADS * 32>>>(qkv,         NQKV, qf, cosb, sinb, HEADS);
    rope_f16<<<S_LEN, KVH * 32>>>(qkv + E_DIM,   NQKV, kf, cosb, sinb, KVH);
    v_expand<<<dim3(NKB_TOT, KVH), 256>>>(qkv, vt);

    // Flash attention (all fp16 operands)
    attn_mma<<<dim3(S_LEN / 128, HEADS), 256, ATTN_SMEM>>>(qf, kf, vt, attf);

    // Output projection (fp16)
    mma_gemm_f16<<<dim3(E_DIM / 128, S_LEN / 128), 256>>>(attf, wof, out, S_LEN, E_DIM, E_DIM);
}

// round 16
// speedup vs baseline: 5.0457x; 1.0599x over previous
#include <cuda_runtime.h>
#include <cuda_bf16.h>
#include <cuda_fp16.h>
#include <cstdint>
#include <math.h>

// Problem constants (B=1, S=2048, E=2048, D=64, H=32, KVH=8, group=4)
#define S_LEN 2048
#define E_DIM 2048
#define HEADS 32
#define KVH 8
#define HDIM 64
#define KV_DIM (KVH * HDIM)        // 512
#define NQKV (E_DIM + 2 * KV_DIM)  // 3072
#define NKB_TOT (S_LEN / 64)       // 32 key blocks

// ---------------------------------------------------------------------------
// Scratch (device globals: runtime allocation is forbidden)
// ---------------------------------------------------------------------------
__device__ float  g_qkv[S_LEN * NQKV];            // fused QKV fp32
__device__ __half g_xf[S_LEN * E_DIM];            // x fp16
__device__ __half g_wqkvf[NQKV * E_DIM];          // Wq|Wk|Wv fp16
__device__ __half g_qf[S_LEN * HEADS * HDIM];     // rope'd Q fp16
__device__ __half g_kf[S_LEN * KVH * HDIM];       // rope'd K fp16
__device__ __half g_vt[KVH * NKB_TOT * 64 * 64];  // V transposed fp16
__device__ __half g_attf[S_LEN * E_DIM];          // attention out fp16
__device__ __half g_wof[E_DIM * E_DIM];           // Wo fp16

__device__ __forceinline__ uint32_t smem_u32(const void* p) {
    uint32_t a;
    asm("{ .reg .u64 t; cvta.to.shared.u64 t, %1; cvt.u32.u64 %0, t; }"
        : "=r"(a) : "l"(p));
    return a;
}

__device__ __forceinline__ uint32_t pack_h2(float lo, float hi) {
    __half2 t = __floats2half2_rn(lo, hi);
    return *reinterpret_cast<uint32_t*>(&t);
}

__device__ __forceinline__ float ex2f(float x) {
    float y;
    asm("ex2.approx.f32 %0, %1;" : "=f"(y) : "f"(x));
    return y;
}

// ---------------------------------------------------------------------------
// Vectorized fp32 -> fp16 conversion (float4 in, 2x half2 out)
// ---------------------------------------------------------------------------
__global__ void conv_f16_v4(const float4* __restrict__ in, uint2* __restrict__ out, int n4)
{
    for (int i = blockIdx.x * blockDim.x + threadIdx.x; i < n4; i += gridDim.x * blockDim.x) {
        float4 v = in[i];
        out[i] = make_uint2(pack_h2(v.x, v.y), pack_h2(v.z, v.w));
    }
}

// 3-segment conversion (Wq | Wk | Wv -> contiguous wqkvf), vectorized
__global__ void conv3_f16_v4(const float4* __restrict__ a, int na4,
                             const float4* __restrict__ b, int nb4,
                             const float4* __restrict__ c, int nc4,
                             uint2* __restrict__ out)
{
    const int n4 = na4 + nb4 + nc4;
    for (int i = blockIdx.x * blockDim.x + threadIdx.x; i < n4; i += gridDim.x * blockDim.x) {
        float4 v;
        if (i < na4)            v = a[i];
        else if (i < na4 + nb4) v = b[i - na4];
        else                    v = c[i - na4 - nb4];
        out[i] = make_uint2(pack_h2(v.x, v.y), pack_h2(v.z, v.w));
    }
}

// ---------------------------------------------------------------------------
// fp16 GEMM via mma.sync: C[M,N] fp32 = A[M,K] @ B[N,K]^T
// 128x128 tile, BK=32, 8 warps, cp.async double buffer, 2 CTAs/SM.
// ---------------------------------------------------------------------------
#define GBK 32
#define ROWB 80
#define TILEB (128 * ROWB)

__global__ __launch_bounds__(256, 2) void mma_gemm_f16(
    const __half* __restrict__ A, const __half* __restrict__ B,
    float* __restrict__ C, int M, int N, int K)
{
    __shared__ __align__(16) uint8_t sm[4 * TILEB];
    const uint32_t sb = smem_u32(sm);

    const int tid  = threadIdx.x;
    const int lane = tid & 31;
    const int wid  = tid >> 5;
    const int wm   = wid & 1;
    const int wn   = wid >> 1;
    const int bm   = blockIdx.y * 128;
    const int bn   = blockIdx.x * 128;

    float acc[4][4][4];
    #pragma unroll
    for (int i = 0; i < 4; i++)
        #pragma unroll
        for (int j = 0; j < 4; j++)
            #pragma unroll
            for (int c = 0; c < 4; c++) acc[i][j][c] = 0.f;

    uint32_t aoff[4], boff[2];
    {
        const int l7 = lane & 7;
        const int rA = ((lane >> 3) & 1) * 8;
        const int kA = ((lane >> 4) & 1) * 16;
        #pragma unroll
        for (int mb = 0; mb < 4; mb++)
            aoff[mb] = (uint32_t)((wm * 64 + mb * 16 + l7 + rA) * ROWB + kA);
        const int rB = ((lane >> 4) & 1) * 8;
        const int kB = ((lane >> 3) & 1) * 16;
        #pragma unroll
        for (int p = 0; p < 2; p++)
            boff[p] = (uint32_t)((wn * 32 + p * 16 + l7 + rB) * ROWB + kB);
    }

    const int NKC = K / GBK;

    auto load_tiles = [&](int k0, int which) {
        uint32_t da = sb + which * TILEB;
        uint32_t db = sb + (2 + which) * TILEB;
        #pragma unroll
        for (int i = 0; i < 2; i++) {
            int c  = tid + 256 * i;
            int r  = c >> 2;
            int cc = c & 3;
            const __half* sa  = A + (size_t)(bm + r) * K + k0 + cc * 8;
            const __half* sbp = B + (size_t)(bn + r) * K + k0 + cc * 8;
            asm volatile("cp.async.cg.shared.global [%0], [%1], 16;"
                         :: "r"(da + r * ROWB + cc * 16), "l"(sa) : "memory");
            asm volatile("cp.async.cg.shared.global [%0], [%1], 16;"
                         :: "r"(db + r * ROWB + cc * 16), "l"(sbp) : "memory");
        }
    };

    load_tiles(0, 0);
    asm volatile("cp.async.commit_group;" ::: "memory");
    load_tiles(GBK, 1);
    asm volatile("cp.async.commit_group;" ::: "memory");

    for (int kc = 0; kc < NKC; kc++) {
        asm volatile("cp.async.wait_group 1;" ::: "memory");
        __syncthreads();

        const int which = kc & 1;
        const uint32_t abuf = sb + which * TILEB;
        const uint32_t bbuf = sb + (2 + which) * TILEB;

        #pragma unroll
        for (int ks = 0; ks < 2; ks++) {
            uint32_t af[4][4], bfr[4][2];
            #pragma unroll
            for (int mb = 0; mb < 4; mb++) {
                asm volatile("ldmatrix.sync.aligned.m8n8.x4.shared.b16 {%0,%1,%2,%3}, [%4];"
                             : "=r"(af[mb][0]), "=r"(af[mb][1]), "=r"(af[mb][2]), "=r"(af[mb][3])
                             : "r"(abuf + aoff[mb] + ks * 32));
            }
            #pragma unroll
            for (int p = 0; p < 2; p++) {
                asm volatile("ldmatrix.sync.aligned.m8n8.x4.shared.b16 {%0,%1,%2,%3}, [%4];"
                             : "=r"(bfr[2 * p][0]), "=r"(bfr[2 * p][1]),
                               "=r"(bfr[2 * p + 1][0]), "=r"(bfr[2 * p + 1][1])
                             : "r"(bbuf + boff[p] + ks * 32));
            }
            #pragma unroll
            for (int mb = 0; mb < 4; mb++)
                #pragma unroll
                for (int nb = 0; nb < 4; nb++) {
                    asm volatile(
                        "mma.sync.aligned.m16n8k16.row.col.f32.f16.f16.f32 "
                        "{%0,%1,%2,%3}, {%4,%5,%6,%7}, {%8,%9}, {%0,%1,%2,%3};"
                        : "+f"(acc[mb][nb][0]), "+f"(acc[mb][nb][1]),
                          "+f"(acc[mb][nb][2]), "+f"(acc[mb][nb][3])
                        : "r"(af[mb][0]), "r"(af[mb][1]), "r"(af[mb][2]), "r"(af[mb][3]),
                          "r"(bfr[nb][0]), "r"(bfr[nb][1]));
                }
        }

        __syncthreads();
        if (kc + 2 < NKC) load_tiles((kc + 2) * GBK, which);
        asm volatile("cp.async.commit_group;" ::: "memory");
    }

    const int g  = lane >> 2;
    const int tc = (lane & 3) * 2;
    #pragma unroll
    for (int mb = 0; mb < 4; mb++) {
        const int row0 = bm + wm * 64 + mb * 16 + g;
        #pragma unroll
        for (int nb = 0; nb < 4; nb++) {
            const int col = bn + wn * 32 + nb * 8 + tc;
            *(float2*)&C[(size_t)row0 * N + col]       = make_float2(acc[mb][nb][0], acc[mb][nb][1]);
            *(float2*)&C[(size_t)(row0 + 8) * N + col] = make_float2(acc[mb][nb][2], acc[mb][nb][3]);
        }
    }
}

// ---------------------------------------------------------------------------
// RoPE -> fp16. src row = s*stride + h*64.
// ---------------------------------------------------------------------------
__global__ void rope_f16(const float* __restrict__ src, int stride,
                         __half* __restrict__ dst,
                         const float* __restrict__ cosb, const float* __restrict__ sinb,
                         int NH)
{
    const int s = blockIdx.x;
    const int h = threadIdx.x >> 5;
    const int d = threadIdx.x & 31;
    const float* p = src + (size_t)s * stride + h * HDIM;
    const float c  = cosb[s * HDIM + d];
    const float sn = sinb[s * HDIM + d];
    const float a = p[d], b = p[d + 32];
    __half* o = dst + ((size_t)s * NH + h) * HDIM;
    o[d]      = __float2half(a * c - b * sn);
    o[d + 32] = __float2half(b * c + a * sn);
}

// ---------------------------------------------------------------------------
// V transpose to fp16: qkv[.., 2560 + kvh*64 + d] -> vt[kvh][kb][d=64][key=64]
// ---------------------------------------------------------------------------
__global__ void v_expand(const float* __restrict__ QKV, __half* __restrict__ vt)
{
    __shared__ float ts[64][65];
    const int kb  = blockIdx.x;
    const int kvh = blockIdx.y;
    const int tid = threadIdx.x;

    #pragma unroll
    for (int i = 0; i < 16; i++) {
        int idx = tid + 256 * i;
        int s = idx >> 6, d = idx & 63;
        ts[s][d] = QKV[(size_t)(kb * 64 + s) * NQKV + E_DIM + KV_DIM + kvh * HDIM + d];
    }
    __syncthreads();

    __half* out = vt + ((size_t)(kvh * NKB_TOT + kb) * 64) * 64;
    #pragma unroll
    for (int i = 0; i < 16; i++) {
        int idx = tid + 256 * i;
        int d = idx >> 6, s = idx & 63;
        out[d * 64 + s] = __float2half(ts[s][d]);
    }
}

// ---------------------------------------------------------------------------
// Flash attention, all-fp16 operands: BQ=128, 8 warps, 3-stage K/V ring.
// ---------------------------------------------------------------------------
#define ROWK 144                       // 64 fp16 = 128B + 16 pad
#define KSTG (64 * ROWK)               // 9216
#define VSTG (64 * ROWK)               // 9216
#define STAGE (KSTG + VSTG)            // 18432
#define ATTN_SMEM (3 * STAGE)          // 55296

__global__ __launch_bounds__(256, 2) void attn_mma(
    const __half* __restrict__ Qf, const __half* __restrict__ Kf,
    const __half* __restrict__ Vt, __half* __restrict__ attf)
{
    extern __shared__ __align__(16) uint8_t sm[];
    const uint32_t sb = smem_u32(sm);

    const int qb  = (int)gridDim.x - 1 - blockIdx.x;   // heavy blocks first
    const int h   = blockIdx.y;
    const int kvh = h >> 2;

    const int tid  = threadIdx.x;
    const int lane = tid & 31;
    const int w    = tid >> 5;

    const int l7  = lane & 7;
    const int l8  = (lane >> 3) & 1;
    const int l16 = (lane >> 4) & 1;
    const int g   = lane >> 2;
    const int t4  = lane & 3;

    const uint32_t qrel = (uint32_t)(w * 16 + l7 + l8 * 8) * ROWK + l16 * 16;
    const uint32_t krel = (uint32_t)(l7 + l16 * 8) * ROWK + l8 * 16;
    const uint32_t vrel = (uint32_t)(l7 + l16 * 8) * ROWK + l8 * 16;

    // ---- stage Q (128 rows x 64 fp16) through smem, move to registers ----
    #pragma unroll
    for (int i = 0; i < 4; i++) {
        int idx = tid + 256 * i;
        int r = idx >> 3, c = idx & 7;
        uint32_t dst = sb + r * ROWK + c * 16;
        const __half* src = Qf + ((size_t)(qb * 128 + r) * HEADS + h) * HDIM + c * 8;
        asm volatile("cp.async.cg.shared.global [%0], [%1], 16;" :: "r"(dst), "l"(src) : "memory");
    }
    asm volatile("cp.async.commit_group;" ::: "memory");
    asm volatile("cp.async.wait_group 0;" ::: "memory");
    __syncthreads();

    uint32_t qf[4][4];
    #pragma unroll
    for (int ks = 0; ks < 4; ks++) {
        asm volatile("ldmatrix.sync.aligned.m8n8.x4.shared.b16 {%0,%1,%2,%3}, [%4];"
                     : "=r"(qf[ks][0]), "=r"(qf[ks][1]), "=r"(qf[ks][2]), "=r"(qf[ks][3])
                     : "r"(sb + qrel + ks * 32));
    }
    __syncthreads();

    const int nkb = 2 * qb + 2;

    auto load_k = [&](int kb_, int s) {
        #pragma unroll
        for (int i = 0; i < 2; i++) {
            int idx = tid + 256 * i;
            int r = idx >> 3, c = idx & 7;
            uint32_t dst = sb + s * STAGE + r * ROWK + c * 16;
            const __half* src = Kf + ((size_t)(kb_ * 64 + r) * KVH + kvh) * HDIM + c * 8;
            asm volatile("cp.async.cg.shared.global [%0], [%1], 16;" :: "r"(dst), "l"(src) : "memory");
        }
    };
    auto load_v = [&](int kb_, int s) {
        const __half* base = Vt + ((size_t)(kvh * NKB_TOT + kb_) * 64) * 64;
        #pragma unroll
        for (int i = 0; i < 2; i++) {
            int idx = tid + 256 * i;
            int r = idx >> 3, c = idx & 7;
            uint32_t dst = sb + s * STAGE + KSTG + r * ROWK + c * 16;
            asm volatile("cp.async.cg.shared.global [%0], [%1], 16;"
                         :: "r"(dst), "l"(base + r * 64 + c * 8) : "memory");
        }
    };

    load_k(0, 0); load_v(0, 0);
    asm volatile("cp.async.commit_group;" ::: "memory");
    load_k(1, 1); load_v(1, 1);
    asm volatile("cp.async.commit_group;" ::: "memory");

    float m0 = -1e30f, m1 = -1e30f, l0 = 0.f, l1 = 0.f;
    float oacc[8][4];
    #pragma unroll
    for (int t = 0; t < 8; t++)
        #pragma unroll
        for (int j = 0; j < 4; j++) oacc[t][j] = 0.f;

    const float sc2 = 0.125f * 1.4426950408889634f;  // scale * log2(e)
    const int row_g0 = qb * 128 + w * 16 + g;
    const int row_g1 = row_g0 + 8;

    for (int kb = 0; kb < nkb; kb++) {
        asm volatile("cp.async.wait_group 1;" ::: "memory");
        __syncthreads();

        if (kb + 2 < nkb) {
            int s2 = (kb + 2) % 3;
            load_k(kb + 2, s2);
            load_v(kb + 2, s2);
        }
        asm volatile("cp.async.commit_group;" ::: "memory");

        const int s = kb % 3;
        const uint32_t koff = sb + s * STAGE + krel;
        const uint32_t voff = sb + s * STAGE + KSTG + vrel;

        // ---- QK (fp16, D=64) ----
        float sacc[8][4];
        #pragma unroll
        for (int t = 0; t < 8; t++)
            #pragma unroll
            for (int j = 0; j < 4; j++) sacc[t][j] = 0.f;

        #pragma unroll
        for (int ks = 0; ks < 4; ks++) {
            uint32_t bq[8][2];
            #pragma unroll
            for (int p = 0; p < 4; p++) {
                asm volatile("ldmatrix.sync.aligned.m8n8.x4.shared.b16 {%0,%1,%2,%3}, [%4];"
                             : "=r"(bq[2 * p][0]), "=r"(bq[2 * p][1]),
                               "=r"(bq[2 * p + 1][0]), "=r"(bq[2 * p + 1][1])
                             : "r"(koff + p * 16 * ROWK + ks * 32));
            }
            #pragma unroll
            for (int t = 0; t < 8; t++) {
                asm volatile(
                    "mma.sync.aligned.m16n8k16.row.col.f32.f16.f16.f32 "
                    "{%0,%1,%2,%3}, {%4,%5,%6,%7}, {%8,%9}, {%0,%1,%2,%3};"
                    : "+f"(sacc[t][0]), "+f"(sacc[t][1]), "+f"(sacc[t][2]), "+f"(sacc[t][3])
                    : "r"(qf[ks][0]), "r"(qf[ks][1]), "r"(qf[ks][2]), "r"(qf[ks][3]),
                      "r"(bq[t][0]), "r"(bq[t][1]));
            }
        }

        // ---- scale (log2 domain) + causal mask ----
        #pragma unroll
        for (int t = 0; t < 8; t++) {
            const int c0 = kb * 64 + t * 8 + 2 * t4;
            sacc[t][0] = (c0     <= row_g0) ? sacc[t][0] * sc2 : -1e30f;
            sacc[t][1] = (c0 + 1 <= row_g0) ? sacc[t][1] * sc2 : -1e30f;
            sacc[t][2] = (c0     <= row_g1) ? sacc[t][2] * sc2 : -1e30f;
            sacc[t][3] = (c0 + 1 <= row_g1) ? sacc[t][3] * sc2 : -1e30f;
        }

        // ---- online softmax (base-2) ----
        float rm0 = -1e30f, rm1 = -1e30f;
        #pragma unroll
        for (int t = 0; t < 8; t++) {
            rm0 = fmaxf(rm0, fmaxf(sacc[t][0], sacc[t][1]));
            rm1 = fmaxf(rm1, fmaxf(sacc[t][2], sacc[t][3]));
        }
        #pragma unroll
        for (int off = 1; off <= 2; off <<= 1) {
            rm0 = fmaxf(rm0, __shfl_xor_sync(0xffffffffu, rm0, off));
            rm1 = fmaxf(rm1, __shfl_xor_sync(0xffffffffu, rm1, off));
        }
        const float mn0 = fmaxf(m0, rm0), mn1 = fmaxf(m1, rm1);
        const float al0 = ex2f(m0 - mn0), al1 = ex2f(m1 - mn1);
        m0 = mn0; m1 = mn1;

        float rs0 = 0.f, rs1 = 0.f;
        #pragma unroll
        for (int t = 0; t < 8; t++) {
            sacc[t][0] = ex2f(sacc[t][0] - mn0);
            sacc[t][1] = ex2f(sacc[t][1] - mn0);
            sacc[t][2] = ex2f(sacc[t][2] - mn1);
            sacc[t][3] = ex2f(sacc[t][3] - mn1);
            rs0 += sacc[t][0] + sacc[t][1];
            rs1 += sacc[t][2] + sacc[t][3];
        }
        #pragma unroll
        for (int off = 1; off <= 2; off <<= 1) {
            rs0 += __shfl_xor_sync(0xffffffffu, rs0, off);
            rs1 += __shfl_xor_sync(0xffffffffu, rs1, off);
        }
        l0 = l0 * al0 + rs0;
        l1 = l1 * al1 + rs1;

        #pragma unroll
        for (int t = 0; t < 8; t++) {
            oacc[t][0] *= al0; oacc[t][1] *= al0;
            oacc[t][2] *= al1; oacc[t][3] *= al1;
        }

        // ---- PV: fp16 single pass ----
        #pragma unroll
        for (int kk = 0; kk < 4; kk++) {
            uint32_t pa0 = pack_h2(sacc[2 * kk][0],     sacc[2 * kk][1]);
            uint32_t pa1 = pack_h2(sacc[2 * kk][2],     sacc[2 * kk][3]);
            uint32_t pa2 = pack_h2(sacc[2 * kk + 1][0], sacc[2 * kk + 1][1]);
            uint32_t pa3 = pack_h2(sacc[2 * kk + 1][2], sacc[2 * kk + 1][3]);

            uint32_t bv[8][2];
            #pragma unroll
            for (int p = 0; p < 4; p++) {
                asm volatile("ldmatrix.sync.aligned.m8n8.x4.shared.b16 {%0,%1,%2,%3}, [%4];"
                             : "=r"(bv[2 * p][0]), "=r"(bv[2 * p][1]),
                               "=r"(bv[2 * p + 1][0]), "=r"(bv[2 * p + 1][1])
                             : "r"(voff + p * 16 * ROWK + kk * 32));
            }
            #pragma unroll
            for (int t = 0; t < 8; t++) {
                asm volatile(
                    "mma.sync.aligned.m16n8k16.row.col.f32.f16.f16.f32 "
                    "{%0,%1,%2,%3}, {%4,%5,%6,%7}, {%8,%9}, {%0,%1,%2,%3};"
                    : "+f"(oacc[t][0]), "+f"(oacc[t][1]), "+f"(oacc[t][2]), "+f"(oacc[t][3])
                    : "r"(pa0), "r"(pa1), "r"(pa2), "r"(pa3), "r"(bv[t][0]), "r"(bv[t][1]));
            }
        }
    }

    // ---- epilogue: normalize, write fp16 rows ----
    const float inv0 = 1.0f / l0;
    const float inv1 = 1.0f / l1;
    #pragma unroll
    for (int t = 0; t < 8; t++) {
        const int col = h * HDIM + t * 8 + 2 * t4;
        *(uint32_t*)(attf + (size_t)row_g0 * E_DIM + col) =
            pack_h2(oacc[t][0] * inv0, oacc[t][1] * inv0);
        *(uint32_t*)(attf + (size_t)row_g1 * E_DIM + col) =
            pack_h2(oacc[t][2] * inv1, oacc[t][3] * inv1);
    }
}

// ---------------------------------------------------------------------------
// Launch. Inputs: 0:x 1:Wq 2:Wk 3:Wv 4:Wo 5:cos 6:sin 7:attn_mask 8:last_pos
// ---------------------------------------------------------------------------
extern "C" void kernel_launch(void* const* d_in, const int* in_sizes, int n_in,
                              void* d_out, int out_size)
{
    const float* x    = (const float*)d_in[0];
    const float* Wq   = (const float*)d_in[1];
    const float* Wk   = (const float*)d_in[2];
    const float* Wv   = (const float*)d_in[3];
    const float* Wo   = (const float*)d_in[4];
    const float* cosb = (const float*)d_in[5];
    const float* sinb = (const float*)d_in[6];
    float* out = (float*)d_out;

    float* qkv;
    __half *xf, *wqkvf, *qf, *kf, *vt, *attf, *wof;
    cudaGetSymbolAddress((void**)&qkv,   g_qkv);
    cudaGetSymbolAddress((void**)&xf,    g_xf);
    cudaGetSymbolAddress((void**)&wqkvf, g_wqkvf);
    cudaGetSymbolAddress((void**)&qf,    g_qf);
    cudaGetSymbolAddress((void**)&kf,    g_kf);
    cudaGetSymbolAddress((void**)&vt,    g_vt);
    cudaGetSymbolAddress((void**)&attf,  g_attf);
    cudaGetSymbolAddress((void**)&wof,   g_wof);

    cudaFuncSetAttribute(attn_mma, cudaFuncAttributeMaxDynamicSharedMemorySize, ATTN_SMEM);

    // fp16 operand prep (vectorized)
    conv_f16_v4<<<1184, 256>>>((const float4*)x,  (uint2*)xf,  S_LEN * E_DIM / 4);
    conv3_f16_v4<<<1184, 256>>>((const float4*)Wq, E_DIM  * E_DIM / 4,
                                (const float4*)Wk, KV_DIM * E_DIM / 4,
                                (const float4*)Wv, KV_DIM * E_DIM / 4,
                                (uint2*)wqkvf);
    conv_f16_v4<<<1184, 256>>>((const float4*)Wo, (uint2*)wof, E_DIM * E_DIM / 4);

    // Fused QKV projection (fp16, K=2048)
    mma_gemm_f16<<<dim3(NQKV / 128, S_LEN / 128), 256>>>(xf, wqkvf, qkv, S_LEN, NQKV, E_DIM);

    // RoPE -> fp16 Q/K; V transpose to fp16
    rope_f16<<<S_LEN, HEADS * 32>>>(qkv,         NQKV, qf, cosb, sinb, HEADS);
    rope_f16<<<S_LEN, KVH * 32>>>(qkv + E_DIM,   NQKV, kf, cosb, sinb, KVH);
    v_expand<<<dim3(NKB_TOT, KVH), 256>>>(qkv, vt);

    // Flash attention (all fp16 operands)
    attn_mma<<<dim3(S_LEN / 128, HEADS), 256, ATTN_SMEM>>>(qf, kf, vt, attf);

    // Output projection (fp16)
    mma_gemm_f16<<<dim3(E_DIM / 128, S_LEN / 128), 256>>>(attf, wof, out, S_LEN, E_DIM, E_DIM);
}